// round 2
// baseline (speedup 1.0000x reference)
#include <cuda_runtime.h>

#define BB 2
#define TT 4096
#define EE 768
#define HH 12
#define DD 64
#define E3 (3*EE)

// Scratch (allocation-free rule: __device__ globals)
__device__ float g_qkv[(size_t)BB*TT*E3];   // [B,T,3E] : q | k | v interleaved per row
__device__ float g_y[(size_t)BB*TT*EE];     // attention output [B,T,E]

// ---------------------------------------------------------------------------
// Generic tiled fp32 GEMM: C[M,N] = A[M,K] @ W[K,N] + bias[N]
// 64x64 tile, BK=16, 256 threads, 4x4 micro-tile per thread.
// ---------------------------------------------------------------------------
__global__ __launch_bounds__(256) void gemm_kernel(
    const float* __restrict__ A, const float* __restrict__ W,
    const float* __restrict__ bias, float* __restrict__ C,
    int M, int N, int K)
{
    __shared__ float As[16][65];  // As[k][m] (transposed for broadcast reads)
    __shared__ float Bs[16][65];  // Bs[k][n]

    const int tid = threadIdx.x;
    const int tx = tid & 15;      // 16 cols of threads
    const int ty = tid >> 4;      // 16 rows of threads
    const int rowBase = blockIdx.y * 64;
    const int colBase = blockIdx.x * 64;

    float acc[4][4] = {};

    for (int k0 = 0; k0 < K; k0 += 16) {
        // load A tile 64x16 (transposed into As[k][m])
        for (int idx = tid; idx < 1024; idx += 256) {
            int m = idx >> 4, kk = idx & 15;
            As[kk][m] = A[(size_t)(rowBase + m) * K + k0 + kk];
        }
        // load W tile 16x64
        for (int idx = tid; idx < 1024; idx += 256) {
            int kk = idx >> 6, n = idx & 63;
            Bs[kk][n] = W[(size_t)(k0 + kk) * N + colBase + n];
        }
        __syncthreads();

#pragma unroll
        for (int kk = 0; kk < 16; kk++) {
            float a[4], b[4];
#pragma unroll
            for (int i = 0; i < 4; i++) a[i] = As[kk][ty * 4 + i];
#pragma unroll
            for (int j = 0; j < 4; j++) b[j] = Bs[kk][tx * 4 + j];
#pragma unroll
            for (int i = 0; i < 4; i++)
#pragma unroll
                for (int j = 0; j < 4; j++)
                    acc[i][j] += a[i] * b[j];
        }
        __syncthreads();
    }

#pragma unroll
    for (int i = 0; i < 4; i++) {
        int r = rowBase + ty * 4 + i;
#pragma unroll
        for (int j = 0; j < 4; j++) {
            int c = colBase + tx * 4 + j;
            C[(size_t)r * N + c] = acc[i][j] + bias[c];
        }
    }
}

// ---------------------------------------------------------------------------
// Flash-attention fp32. One block = one (b,h,q-tile of 64). 256 threads.
// S tile 64x64 computed in registers (4x4/thread), online softmax,
// P staged through smem for the PV mini-GEMM.
// ---------------------------------------------------------------------------
#define PP 65               // smem row pitch (pad for bank conflicts)
#define ATTN_SMEM (4 * 64 * PP * (int)sizeof(float))   // Q,K,V,P = 66560 B

__global__ __launch_bounds__(256) void attn_kernel()
{
    extern __shared__ float smem[];
    float* Qs = smem;
    float* Ks = smem + 64 * PP;
    float* Vs = smem + 2 * 64 * PP;
    float* Ps = smem + 3 * 64 * PP;

    const int tid = threadIdx.x;
    const int tx = tid & 15;
    const int ty = tid >> 4;
    const int qt = blockIdx.x;          // q tile index
    const int bh = blockIdx.y;
    const int b = bh / HH, h = bh % HH;
    const int q0 = qt * 64;
    const float scale = 0.125f;         // 1/sqrt(64)

    const size_t base = (size_t)b * TT * E3 + (size_t)h * DD;

    // load Q tile [64 rows x 64 d]
    for (int idx = tid; idx < 64 * 64; idx += 256) {
        int r = idx >> 6, c = idx & 63;
        Qs[r * PP + c] = g_qkv[base + (size_t)(q0 + r) * E3 + c];
    }

    float m[4], l[4], acc[4][4];
#pragma unroll
    for (int i = 0; i < 4; i++) {
        m[i] = -1e30f; l[i] = 0.f;
#pragma unroll
        for (int j = 0; j < 4; j++) acc[i][j] = 0.f;
    }

    for (int jt = 0; jt <= qt; jt++) {
        const int k0 = jt * 64;
        // load K and V tiles
        for (int idx = tid; idx < 64 * 64; idx += 256) {
            int r = idx >> 6, c = idx & 63;
            size_t row = base + (size_t)(k0 + r) * E3;
            Ks[r * PP + c] = g_qkv[row + EE + c];
            Vs[r * PP + c] = g_qkv[row + 2 * EE + c];
        }
        __syncthreads();

        // S = Q K^T  (4x4 per thread)
        float s[4][4] = {};
#pragma unroll
        for (int kk = 0; kk < 64; kk++) {
            float qv[4], kv[4];
#pragma unroll
            for (int i = 0; i < 4; i++) qv[i] = Qs[(ty * 4 + i) * PP + kk];
#pragma unroll
            for (int j = 0; j < 4; j++) kv[j] = Ks[(tx * 4 + j) * PP + kk];
#pragma unroll
            for (int i = 0; i < 4; i++)
#pragma unroll
                for (int j = 0; j < 4; j++)
                    s[i][j] += qv[i] * kv[j];
        }

        const bool diag = (jt == qt);
#pragma unroll
        for (int i = 0; i < 4; i++) {
            int qr = q0 + ty * 4 + i;
#pragma unroll
            for (int j = 0; j < 4; j++) {
                s[i][j] *= scale;
                if (diag && (k0 + tx * 4 + j) > qr) s[i][j] = -1e30f;
            }
        }

        // online softmax per row (reduce across the 16 tx lanes)
#pragma unroll
        for (int i = 0; i < 4; i++) {
            float mx = fmaxf(fmaxf(s[i][0], s[i][1]), fmaxf(s[i][2], s[i][3]));
#pragma unroll
            for (int off = 8; off; off >>= 1)
                mx = fmaxf(mx, __shfl_xor_sync(0xffffffffu, mx, off));
            float mnew = fmaxf(m[i], mx);
            float alpha = __expf(m[i] - mnew);
            m[i] = mnew;
            float sum = 0.f;
#pragma unroll
            for (int j = 0; j < 4; j++) {
                s[i][j] = __expf(s[i][j] - mnew);
                sum += s[i][j];
                Ps[(ty * 4 + i) * PP + tx * 4 + j] = s[i][j];
            }
#pragma unroll
            for (int off = 8; off; off >>= 1)
                sum += __shfl_xor_sync(0xffffffffu, sum, off);
            l[i] = l[i] * alpha + sum;
#pragma unroll
            for (int j = 0; j < 4; j++) acc[i][j] *= alpha;
        }
        __syncthreads();

        // acc += P @ V
#pragma unroll
        for (int kk = 0; kk < 64; kk++) {
            float pv[4], vv[4];
#pragma unroll
            for (int i = 0; i < 4; i++) pv[i] = Ps[(ty * 4 + i) * PP + kk];
#pragma unroll
            for (int j = 0; j < 4; j++) vv[j] = Vs[kk * PP + tx * 4 + j];
#pragma unroll
            for (int i = 0; i < 4; i++)
#pragma unroll
                for (int j = 0; j < 4; j++)
                    acc[i][j] += pv[i] * vv[j];
        }
        __syncthreads();
    }

    // write normalized output: y[b, q0+r, h*64 + c]
#pragma unroll
    for (int i = 0; i < 4; i++) {
        int r = q0 + ty * 4 + i;
        float inv = 1.0f / l[i];
#pragma unroll
        for (int j = 0; j < 4; j++) {
            int c = h * DD + tx * 4 + j;
            g_y[((size_t)b * TT + r) * EE + c] = acc[i][j] * inv;
        }
    }
}

// ---------------------------------------------------------------------------
extern "C" void kernel_launch(void* const* d_in, const int* in_sizes, int n_in,
                              void* d_out, int out_size)
{
    const float* x      = (const float*)d_in[0];
    const float* W_attn = (const float*)d_in[1];
    const float* b_attn = (const float*)d_in[2];
    const float* W_proj = (const float*)d_in[3];
    const float* b_proj = (const float*)d_in[4];
    float* out = (float*)d_out;

    float *qkv, *y;
    cudaGetSymbolAddress((void**)&qkv, g_qkv);
    cudaGetSymbolAddress((void**)&y, g_y);

    // 1) QKV projection: [B*T, E] @ [E, 3E] + b  -> g_qkv
    gemm_kernel<<<dim3(E3 / 64, (BB * TT) / 64), 256>>>(
        x, W_attn, b_attn, qkv, BB * TT, E3, EE);

    // 2) causal flash attention -> g_y
    cudaFuncSetAttribute(attn_kernel,
                         cudaFuncAttributeMaxDynamicSharedMemorySize, ATTN_SMEM);
    attn_kernel<<<dim3(TT / 64, BB * HH), 256, ATTN_SMEM>>>();

    // 3) output projection: [B*T, E] @ [E, E] + b -> d_out
    gemm_kernel<<<dim3(EE / 64, (BB * TT) / 64), 256>>>(
        y, W_proj, b_proj, out, BB * TT, EE, EE);
}

// round 3
// speedup vs baseline: 3.4582x; 3.4582x over previous
#include <cuda_runtime.h>

#define BB 2
#define TT 4096
#define EE 768
#define HH 12
#define DD 64
#define E3 (3*EE)

// Scratch (allocation-free rule: __device__ globals)
__device__ float g_qkv[(size_t)BB*TT*E3];   // [B,T,3E] : q | k | v per row
__device__ float g_y[(size_t)BB*TT*EE];     // attention output [B,T,E]

// ---------------------------------------------------------------------------
// TF32 helpers
// ---------------------------------------------------------------------------
__device__ __forceinline__ unsigned f2tf(float x) {
    unsigned u;
    asm("cvt.rna.tf32.f32 %0, %1;" : "=r"(u) : "f"(x));
    return u;
}

#define MMA_TF32(c, a0, a1, a2, a3, b0, b1)                                   \
    asm volatile(                                                             \
        "mma.sync.aligned.m16n8k8.row.col.f32.tf32.tf32.f32 "                 \
        "{%0,%1,%2,%3},{%4,%5,%6,%7},{%8,%9},{%0,%1,%2,%3};"                  \
        : "+f"((c)[0]), "+f"((c)[1]), "+f"((c)[2]), "+f"((c)[3])              \
        : "r"(a0), "r"(a1), "r"(a2), "r"(a3), "r"(b0), "r"(b1))

// ---------------------------------------------------------------------------
// TF32 GEMM: C[M,N] = A[M,K] @ W[K,N] + bias[N]
// 128x128 block tile, BK=32, 256 threads (8 warps), warp tile 32x64.
// A fragments: smem pitch 36 (banks 4r+c conflict-free).
// B fragments: smem pitch 136 (banks 8k+n conflict-free).
// ---------------------------------------------------------------------------
#define APITCH 36
#define BPITCH 136

__global__ __launch_bounds__(256) void gemm_tf32_kernel(
    const float* __restrict__ A, const float* __restrict__ W,
    const float* __restrict__ bias, float* __restrict__ C,
    int M, int N, int K)
{
    __shared__ unsigned As[128 * APITCH];   // [m][k] tf32
    __shared__ unsigned Bs[32 * BPITCH];    // [k][n] tf32

    const int tid  = threadIdx.x;
    const int lane = tid & 31;
    const int warp = tid >> 5;
    const int grp  = lane >> 2;       // groupID (row within fragment)
    const int tid4 = lane & 3;        // threadID_in_group
    const int wm = warp & 3;          // 4 warps along M  -> rows wm*32
    const int wn = warp >> 2;         // 2 warps along N  -> cols wn*64
    const int rowBase = blockIdx.y * 128;
    const int colBase = blockIdx.x * 128;

    float acc[2][8][4];
#pragma unroll
    for (int mt = 0; mt < 2; mt++)
#pragma unroll
        for (int nt = 0; nt < 8; nt++)
#pragma unroll
            for (int c = 0; c < 4; c++) acc[mt][nt][c] = 0.f;

    for (int k0 = 0; k0 < K; k0 += 32) {
        // A tile 128x32 -> As (tf32), vectorized
#pragma unroll
        for (int i = tid; i < 1024; i += 256) {
            int r = i >> 3, c4 = (i & 7) << 2;
            float4 v = *(const float4*)&A[(size_t)(rowBase + r) * K + k0 + c4];
            unsigned* d = &As[r * APITCH + c4];
            d[0] = f2tf(v.x); d[1] = f2tf(v.y); d[2] = f2tf(v.z); d[3] = f2tf(v.w);
        }
        // W tile 32x128 -> Bs (tf32)
#pragma unroll
        for (int i = tid; i < 1024; i += 256) {
            int r = i >> 5, c4 = (i & 31) << 2;
            float4 v = *(const float4*)&W[(size_t)(k0 + r) * N + colBase + c4];
            unsigned* d = &Bs[r * BPITCH + c4];
            d[0] = f2tf(v.x); d[1] = f2tf(v.y); d[2] = f2tf(v.z); d[3] = f2tf(v.w);
        }
        __syncthreads();

#pragma unroll
        for (int kb = 0; kb < 32; kb += 8) {
            unsigned a[2][4];
#pragma unroll
            for (int mt = 0; mt < 2; mt++) {
                int mr = wm * 32 + mt * 16;
                a[mt][0] = As[(mr + grp)     * APITCH + kb + tid4];
                a[mt][1] = As[(mr + grp + 8) * APITCH + kb + tid4];
                a[mt][2] = As[(mr + grp)     * APITCH + kb + tid4 + 4];
                a[mt][3] = As[(mr + grp + 8) * APITCH + kb + tid4 + 4];
            }
#pragma unroll
            for (int nt = 0; nt < 8; nt++) {
                int nc = wn * 64 + nt * 8;
                unsigned b0 = Bs[(kb + tid4)     * BPITCH + nc + grp];
                unsigned b1 = Bs[(kb + tid4 + 4) * BPITCH + nc + grp];
                MMA_TF32(acc[0][nt], a[0][0], a[0][1], a[0][2], a[0][3], b0, b1);
                MMA_TF32(acc[1][nt], a[1][0], a[1][1], a[1][2], a[1][3], b0, b1);
            }
        }
        __syncthreads();
    }

    // epilogue: + bias, float2 stores
#pragma unroll
    for (int mt = 0; mt < 2; mt++) {
        int r0 = rowBase + wm * 32 + mt * 16 + grp;
        int r1 = r0 + 8;
#pragma unroll
        for (int nt = 0; nt < 8; nt++) {
            int col = colBase + wn * 64 + nt * 8 + 2 * tid4;
            float bx = bias[col], by = bias[col + 1];
            float2 o0 = { acc[mt][nt][0] + bx, acc[mt][nt][1] + by };
            float2 o1 = { acc[mt][nt][2] + bx, acc[mt][nt][3] + by };
            *(float2*)&C[(size_t)r0 * N + col] = o0;
            *(float2*)&C[(size_t)r1 * N + col] = o1;
        }
    }
}

// ---------------------------------------------------------------------------
// Flash attention, TF32 tensor cores.
// Block = (b, h, 64-row q tile). 128 threads = 4 warps, warp owns 16 q rows.
// Q/K/V/P in smem as tf32 (pitch 72: conflict-free for all fragment patterns).
// ---------------------------------------------------------------------------
#define SP 72
#define Q_OFF 0
#define K_OFF (64 * SP)
#define V_OFF (2 * 64 * SP)
#define P_OFF (3 * 64 * SP)
#define ATTN_SMEM (4 * 64 * SP * (int)sizeof(unsigned))   // 73728 B

__global__ __launch_bounds__(128) void attn_tf32_kernel()
{
    extern __shared__ unsigned su[];

    const int tid  = threadIdx.x;
    const int lane = tid & 31;
    const int warp = tid >> 5;          // 0..3, 16 q rows each
    const int grp  = lane >> 2;
    const int tid4 = lane & 3;
    const int w16  = warp * 16;

    const int qt = blockIdx.x;
    const int bh = blockIdx.y;
    const int b = bh / HH, h = bh % HH;
    const int q0 = qt * 64;
    const float scale = 0.125f;         // 1/sqrt(64)

    const size_t base = (size_t)b * TT * E3 + (size_t)h * DD;

    // load Q tile (64x64) -> tf32 smem
#pragma unroll
    for (int i = tid; i < 1024; i += 128) {
        int r = i >> 4, c4 = (i & 15) << 2;
        float4 v = *(const float4*)&g_qkv[base + (size_t)(q0 + r) * E3 + c4];
        unsigned* d = &su[Q_OFF + r * SP + c4];
        d[0] = f2tf(v.x); d[1] = f2tf(v.y); d[2] = f2tf(v.z); d[3] = f2tf(v.w);
    }

    float oacc[8][4];
    float mrow[2] = { -1e30f, -1e30f };
    float lrow[2] = { 0.f, 0.f };
#pragma unroll
    for (int nt = 0; nt < 8; nt++)
#pragma unroll
        for (int c = 0; c < 4; c++) oacc[nt][c] = 0.f;

    __syncthreads();

    for (int jt = 0; jt <= qt; jt++) {
        const int k0 = jt * 64;
        // load K, V tiles -> tf32 smem
#pragma unroll
        for (int i = tid; i < 1024; i += 128) {
            int r = i >> 4, c4 = (i & 15) << 2;
            size_t row = base + (size_t)(k0 + r) * E3;
            float4 kv = *(const float4*)&g_qkv[row + EE + c4];
            float4 vv = *(const float4*)&g_qkv[row + 2 * EE + c4];
            unsigned* dk = &su[K_OFF + r * SP + c4];
            unsigned* dv = &su[V_OFF + r * SP + c4];
            dk[0] = f2tf(kv.x); dk[1] = f2tf(kv.y); dk[2] = f2tf(kv.z); dk[3] = f2tf(kv.w);
            dv[0] = f2tf(vv.x); dv[1] = f2tf(vv.y); dv[2] = f2tf(vv.z); dv[3] = f2tf(vv.w);
        }
        __syncthreads();

        // ---- S = Q K^T  (warp: 16 x 64) ----
        float sacc[8][4];
#pragma unroll
        for (int nt = 0; nt < 8; nt++)
#pragma unroll
            for (int c = 0; c < 4; c++) sacc[nt][c] = 0.f;

#pragma unroll
        for (int kb = 0; kb < 64; kb += 8) {
            unsigned a0 = su[Q_OFF + (w16 + grp)     * SP + kb + tid4];
            unsigned a1 = su[Q_OFF + (w16 + grp + 8) * SP + kb + tid4];
            unsigned a2 = su[Q_OFF + (w16 + grp)     * SP + kb + tid4 + 4];
            unsigned a3 = su[Q_OFF + (w16 + grp + 8) * SP + kb + tid4 + 4];
#pragma unroll
            for (int nt = 0; nt < 8; nt++) {
                unsigned b0 = su[K_OFF + (nt * 8 + grp) * SP + kb + tid4];
                unsigned b1 = su[K_OFF + (nt * 8 + grp) * SP + kb + tid4 + 4];
                MMA_TF32(sacc[nt], a0, a1, a2, a3, b0, b1);
            }
        }

        // scale + causal mask (only diagonal tile can mask)
        const bool diag = (jt == qt);
#pragma unroll
        for (int nt = 0; nt < 8; nt++)
#pragma unroll
            for (int c = 0; c < 4; c++) {
                float v = sacc[nt][c] * scale;
                if (diag) {
                    int row = q0 + w16 + grp + 8 * (c >> 1);
                    int col = k0 + nt * 8 + 2 * tid4 + (c & 1);
                    if (col > row) v = -1e30f;
                }
                sacc[nt][c] = v;
            }

        // ---- online softmax (row spread over 4-lane group) ----
#pragma unroll
        for (int p = 0; p < 2; p++) {
            float mx = -1e30f;
#pragma unroll
            for (int nt = 0; nt < 8; nt++)
                mx = fmaxf(mx, fmaxf(sacc[nt][2 * p], sacc[nt][2 * p + 1]));
            mx = fmaxf(mx, __shfl_xor_sync(0xffffffffu, mx, 1));
            mx = fmaxf(mx, __shfl_xor_sync(0xffffffffu, mx, 2));
            float mnew = fmaxf(mrow[p], mx);
            float alpha = __expf(mrow[p] - mnew);
            mrow[p] = mnew;
            float sum = 0.f;
            int rloc = w16 + grp + 8 * p;
#pragma unroll
            for (int nt = 0; nt < 8; nt++) {
                float p0 = __expf(sacc[nt][2 * p]     - mnew);
                float p1 = __expf(sacc[nt][2 * p + 1] - mnew);
                sum += p0 + p1;
                su[P_OFF + rloc * SP + nt * 8 + 2 * tid4]     = f2tf(p0);
                su[P_OFF + rloc * SP + nt * 8 + 2 * tid4 + 1] = f2tf(p1);
            }
            sum += __shfl_xor_sync(0xffffffffu, sum, 1);
            sum += __shfl_xor_sync(0xffffffffu, sum, 2);
            lrow[p] = lrow[p] * alpha + sum;
#pragma unroll
            for (int nt = 0; nt < 8; nt++) {
                oacc[nt][2 * p]     *= alpha;
                oacc[nt][2 * p + 1] *= alpha;
            }
        }
        __syncwarp();   // P is warp-local (warp reads only its own 16 rows)

        // ---- O += P V  (warp: 16 x 64, k over 64 key positions) ----
#pragma unroll
        for (int kb = 0; kb < 64; kb += 8) {
            unsigned a0 = su[P_OFF + (w16 + grp)     * SP + kb + tid4];
            unsigned a1 = su[P_OFF + (w16 + grp + 8) * SP + kb + tid4];
            unsigned a2 = su[P_OFF + (w16 + grp)     * SP + kb + tid4 + 4];
            unsigned a3 = su[P_OFF + (w16 + grp + 8) * SP + kb + tid4 + 4];
#pragma unroll
            for (int nt = 0; nt < 8; nt++) {
                unsigned b0 = su[V_OFF + (kb + tid4)     * SP + nt * 8 + grp];
                unsigned b1 = su[V_OFF + (kb + tid4 + 4) * SP + nt * 8 + grp];
                MMA_TF32(oacc[nt], a0, a1, a2, a3, b0, b1);
            }
        }
        __syncthreads();   // before next K/V overwrite
    }

    // epilogue: normalize, write y[b, row, h*64 + col]
    float inv0 = 1.0f / lrow[0];
    float inv1 = 1.0f / lrow[1];
    int r0 = q0 + w16 + grp;
    int r1 = r0 + 8;
#pragma unroll
    for (int nt = 0; nt < 8; nt++) {
        int col = h * DD + nt * 8 + 2 * tid4;
        float2 o0 = { oacc[nt][0] * inv0, oacc[nt][1] * inv0 };
        float2 o1 = { oacc[nt][2] * inv1, oacc[nt][3] * inv1 };
        *(float2*)&g_y[((size_t)b * TT + r0) * EE + col] = o0;
        *(float2*)&g_y[((size_t)b * TT + r1) * EE + col] = o1;
    }
}

// ---------------------------------------------------------------------------
extern "C" void kernel_launch(void* const* d_in, const int* in_sizes, int n_in,
                              void* d_out, int out_size)
{
    const float* x      = (const float*)d_in[0];
    const float* W_attn = (const float*)d_in[1];
    const float* b_attn = (const float*)d_in[2];
    const float* W_proj = (const float*)d_in[3];
    const float* b_proj = (const float*)d_in[4];
    float* out = (float*)d_out;

    float *qkv, *y;
    cudaGetSymbolAddress((void**)&qkv, g_qkv);
    cudaGetSymbolAddress((void**)&y, g_y);

    // 1) QKV projection: [8192, 768] @ [768, 2304] + b
    gemm_tf32_kernel<<<dim3(E3 / 128, (BB * TT) / 128), 256>>>(
        x, W_attn, b_attn, qkv, BB * TT, E3, EE);

    // 2) causal flash attention (TF32 MMA)
    static int attn_attr_set = 0;
    cudaFuncSetAttribute(attn_tf32_kernel,
                         cudaFuncAttributeMaxDynamicSharedMemorySize, ATTN_SMEM);
    (void)attn_attr_set;
    attn_tf32_kernel<<<dim3(TT / 64, BB * HH), 128, ATTN_SMEM>>>();

    // 3) output projection: [8192, 768] @ [768, 768] + b
    gemm_tf32_kernel<<<dim3(EE / 128, (BB * TT) / 128), 256>>>(
        y, W_proj, b_proj, out, BB * TT, EE, EE);
}

// round 4
// speedup vs baseline: 3.7323x; 1.0793x over previous
#include <cuda_runtime.h>

#define BB 2
#define TT 4096
#define EE 768
#define HH 12
#define DD 64
#define E3 (3*EE)

// Scratch (allocation-free rule: __device__ globals)
__device__ float g_qkv[(size_t)BB*TT*E3];   // [B,T,3E] : q | k | v per row
__device__ float g_y[(size_t)BB*TT*EE];     // attention output [B,T,E]

// ---------------------------------------------------------------------------
// TF32 helpers
// ---------------------------------------------------------------------------
__device__ __forceinline__ unsigned f2tf(float x) {
    unsigned u;
    asm("cvt.rna.tf32.f32 %0, %1;" : "=r"(u) : "f"(x));
    return u;
}

#define MMA_TF32(c, a0, a1, a2, a3, b0, b1)                                   \
    asm volatile(                                                             \
        "mma.sync.aligned.m16n8k8.row.col.f32.tf32.tf32.f32 "                 \
        "{%0,%1,%2,%3},{%4,%5,%6,%7},{%8,%9},{%0,%1,%2,%3};"                  \
        : "+f"((c)[0]), "+f"((c)[1]), "+f"((c)[2]), "+f"((c)[3])              \
        : "r"(a0), "r"(a1), "r"(a2), "r"(a3), "r"(b0), "r"(b1))

// ---------------------------------------------------------------------------
// TF32 GEMM: C[M,N] = A[M,K] @ W[K,N] + bias[N]
// 128x128 block tile, BK=32, 256 threads (8 warps), warp tile 32x64.
// ---------------------------------------------------------------------------
#define APITCH 36
#define BPITCH 136

__global__ __launch_bounds__(256, 2) void gemm_tf32_kernel(
    const float* __restrict__ A, const float* __restrict__ W,
    const float* __restrict__ bias, float* __restrict__ C,
    int M, int N, int K)
{
    __shared__ unsigned As[128 * APITCH];   // [m][k] tf32
    __shared__ unsigned Bs[32 * BPITCH];    // [k][n] tf32

    const int tid  = threadIdx.x;
    const int lane = tid & 31;
    const int warp = tid >> 5;
    const int grp  = lane >> 2;       // groupID (row within fragment)
    const int tid4 = lane & 3;        // threadID_in_group
    const int wm = warp & 3;          // 4 warps along M  -> rows wm*32
    const int wn = warp >> 2;         // 2 warps along N  -> cols wn*64
    const int rowBase = blockIdx.y * 128;
    const int colBase = blockIdx.x * 128;

    float acc[2][8][4];
#pragma unroll
    for (int mt = 0; mt < 2; mt++)
#pragma unroll
        for (int nt = 0; nt < 8; nt++)
#pragma unroll
            for (int c = 0; c < 4; c++) acc[mt][nt][c] = 0.f;

    for (int k0 = 0; k0 < K; k0 += 32) {
        // A tile 128x32 -> As (tf32), vectorized
#pragma unroll
        for (int i = tid; i < 1024; i += 256) {
            int r = i >> 3, c4 = (i & 7) << 2;
            float4 v = *(const float4*)&A[(size_t)(rowBase + r) * K + k0 + c4];
            unsigned* d = &As[r * APITCH + c4];
            d[0] = f2tf(v.x); d[1] = f2tf(v.y); d[2] = f2tf(v.z); d[3] = f2tf(v.w);
        }
        // W tile 32x128 -> Bs (tf32)
#pragma unroll
        for (int i = tid; i < 1024; i += 256) {
            int r = i >> 5, c4 = (i & 31) << 2;
            float4 v = *(const float4*)&W[(size_t)(k0 + r) * N + colBase + c4];
            unsigned* d = &Bs[r * BPITCH + c4];
            d[0] = f2tf(v.x); d[1] = f2tf(v.y); d[2] = f2tf(v.z); d[3] = f2tf(v.w);
        }
        __syncthreads();

#pragma unroll
        for (int kb = 0; kb < 32; kb += 8) {
            unsigned a[2][4];
#pragma unroll
            for (int mt = 0; mt < 2; mt++) {
                int mr = wm * 32 + mt * 16;
                a[mt][0] = As[(mr + grp)     * APITCH + kb + tid4];
                a[mt][1] = As[(mr + grp + 8) * APITCH + kb + tid4];
                a[mt][2] = As[(mr + grp)     * APITCH + kb + tid4 + 4];
                a[mt][3] = As[(mr + grp + 8) * APITCH + kb + tid4 + 4];
            }
#pragma unroll
            for (int nt = 0; nt < 8; nt++) {
                int nc = wn * 64 + nt * 8;
                unsigned b0 = Bs[(kb + tid4)     * BPITCH + nc + grp];
                unsigned b1 = Bs[(kb + tid4 + 4) * BPITCH + nc + grp];
                MMA_TF32(acc[0][nt], a[0][0], a[0][1], a[0][2], a[0][3], b0, b1);
                MMA_TF32(acc[1][nt], a[1][0], a[1][1], a[1][2], a[1][3], b0, b1);
            }
        }
        __syncthreads();
    }

    // epilogue: + bias, float2 stores
#pragma unroll
    for (int mt = 0; mt < 2; mt++) {
        int r0 = rowBase + wm * 32 + mt * 16 + grp;
        int r1 = r0 + 8;
#pragma unroll
        for (int nt = 0; nt < 8; nt++) {
            int col = colBase + wn * 64 + nt * 8 + 2 * tid4;
            float bx = bias[col], by = bias[col + 1];
            float2 o0 = { acc[mt][nt][0] + bx, acc[mt][nt][1] + by };
            float2 o1 = { acc[mt][nt][2] + bx, acc[mt][nt][3] + by };
            *(float2*)&C[(size_t)r0 * N + col] = o0;
            *(float2*)&C[(size_t)r1 * N + col] = o1;
        }
    }
}

// ---------------------------------------------------------------------------
// Flash attention, TF32 tensor cores.
// Block = (b, h, 128-row q tile). 256 threads = 8 warps, warp owns 16 q rows.
// K/V streamed as 64-key tiles. Softmax scale folded into Q at load.
// Pitches: Q/K/P = 68 (=4 mod 32, conflict-free A-frag & K B-frag loads),
//          V = 72 (=8 mod 32, conflict-free V B-frag loads).
// ---------------------------------------------------------------------------
#define QP 68
#define KP 68
#define VP 72
#define Q_OFF 0
#define K_OFF (128 * QP)                 // 8704
#define V_OFF (K_OFF + 64 * KP)          // 13056
#define P_OFF (V_OFF + 64 * VP)          // 17664
#define ATTN_SMEM ((P_OFF + 128 * QP) * (int)sizeof(unsigned))   // 105472 B

__global__ __launch_bounds__(256, 2) void attn_tf32_kernel()
{
    extern __shared__ unsigned su[];

    const int tid  = threadIdx.x;
    const int lane = tid & 31;
    const int warp = tid >> 5;          // 0..7, 16 q rows each
    const int grp  = lane >> 2;
    const int tid4 = lane & 3;
    const int w16  = warp * 16;

    const int qt = blockIdx.x;
    const int bh = blockIdx.y;
    const int b = bh / HH, h = bh % HH;
    const int q0 = qt * 128;

    const size_t base = (size_t)b * TT * E3 + (size_t)h * DD;

    // load Q tile (128x64) -> tf32 smem, scale folded in
#pragma unroll
    for (int i = tid; i < 2048; i += 256) {
        int r = i >> 4, c4 = (i & 15) << 2;
        float4 v = *(const float4*)&g_qkv[base + (size_t)(q0 + r) * E3 + c4];
        unsigned* d = &su[Q_OFF + r * QP + c4];
        d[0] = f2tf(v.x * 0.125f); d[1] = f2tf(v.y * 0.125f);
        d[2] = f2tf(v.z * 0.125f); d[3] = f2tf(v.w * 0.125f);
    }

    float oacc[8][4];
    float mrow[2] = { -1e30f, -1e30f };
    float lrow[2] = { 0.f, 0.f };
#pragma unroll
    for (int nt = 0; nt < 8; nt++)
#pragma unroll
        for (int c = 0; c < 4; c++) oacc[nt][c] = 0.f;

    const int njt = 2 * qt + 2;
    for (int jt = 0; jt < njt; jt++) {
        const int k0 = jt * 64;
        // load K, V tiles (64x64) -> tf32 smem
#pragma unroll
        for (int i = tid; i < 1024; i += 256) {
            int r = i >> 4, c4 = (i & 15) << 2;
            size_t row = base + (size_t)(k0 + r) * E3;
            float4 kv = *(const float4*)&g_qkv[row + EE + c4];
            float4 vv = *(const float4*)&g_qkv[row + 2 * EE + c4];
            unsigned* dk = &su[K_OFF + r * KP + c4];
            unsigned* dv = &su[V_OFF + r * VP + c4];
            dk[0] = f2tf(kv.x); dk[1] = f2tf(kv.y); dk[2] = f2tf(kv.z); dk[3] = f2tf(kv.w);
            dv[0] = f2tf(vv.x); dv[1] = f2tf(vv.y); dv[2] = f2tf(vv.z); dv[3] = f2tf(vv.w);
        }
        __syncthreads();

        // warp fully masked for this k tile? (rows q0+w16 .. q0+w16+15)
        const bool active = (k0 <= q0 + w16 + 15);
        if (active) {
            // ---- S = Q K^T  (warp: 16 x 64) ----
            float sacc[8][4];
#pragma unroll
            for (int nt = 0; nt < 8; nt++)
#pragma unroll
                for (int c = 0; c < 4; c++) sacc[nt][c] = 0.f;

#pragma unroll
            for (int kb = 0; kb < 64; kb += 8) {
                unsigned a0 = su[Q_OFF + (w16 + grp)     * QP + kb + tid4];
                unsigned a1 = su[Q_OFF + (w16 + grp + 8) * QP + kb + tid4];
                unsigned a2 = su[Q_OFF + (w16 + grp)     * QP + kb + tid4 + 4];
                unsigned a3 = su[Q_OFF + (w16 + grp + 8) * QP + kb + tid4 + 4];
#pragma unroll
                for (int nt = 0; nt < 8; nt++) {
                    unsigned b0 = su[K_OFF + (nt * 8 + grp) * KP + kb + tid4];
                    unsigned b1 = su[K_OFF + (nt * 8 + grp) * KP + kb + tid4 + 4];
                    MMA_TF32(sacc[nt], a0, a1, a2, a3, b0, b1);
                }
            }

            // causal mask (only tiles overlapping the diagonal region)
            if (k0 + 63 > q0 + w16) {
#pragma unroll
                for (int nt = 0; nt < 8; nt++)
#pragma unroll
                    for (int c = 0; c < 4; c++) {
                        int row = q0 + w16 + grp + 8 * (c >> 1);
                        int col = k0 + nt * 8 + 2 * tid4 + (c & 1);
                        if (col > row) sacc[nt][c] = -1e30f;
                    }
            }

            // ---- online softmax (row spread over 4-lane group) ----
#pragma unroll
            for (int p = 0; p < 2; p++) {
                float mx = -1e30f;
#pragma unroll
                for (int nt = 0; nt < 8; nt++)
                    mx = fmaxf(mx, fmaxf(sacc[nt][2 * p], sacc[nt][2 * p + 1]));
                mx = fmaxf(mx, __shfl_xor_sync(0xffffffffu, mx, 1));
                mx = fmaxf(mx, __shfl_xor_sync(0xffffffffu, mx, 2));
                float mnew = fmaxf(mrow[p], mx);
                float alpha = __expf(mrow[p] - mnew);
                mrow[p] = mnew;
                float sum = 0.f;
                int rloc = w16 + grp + 8 * p;
#pragma unroll
                for (int nt = 0; nt < 8; nt++) {
                    float p0 = __expf(sacc[nt][2 * p]     - mnew);
                    float p1 = __expf(sacc[nt][2 * p + 1] - mnew);
                    sum += p0 + p1;
                    uint2 pk = { f2tf(p0), f2tf(p1) };
                    *(uint2*)&su[P_OFF + rloc * QP + nt * 8 + 2 * tid4] = pk;
                }
                sum += __shfl_xor_sync(0xffffffffu, sum, 1);
                sum += __shfl_xor_sync(0xffffffffu, sum, 2);
                lrow[p] = lrow[p] * alpha + sum;
#pragma unroll
                for (int nt = 0; nt < 8; nt++) {
                    oacc[nt][2 * p]     *= alpha;
                    oacc[nt][2 * p + 1] *= alpha;
                }
            }
            __syncwarp();   // P is warp-local

            // ---- O += P V  (warp: 16 x 64) ----
#pragma unroll
            for (int kb = 0; kb < 64; kb += 8) {
                unsigned a0 = su[P_OFF + (w16 + grp)     * QP + kb + tid4];
                unsigned a1 = su[P_OFF + (w16 + grp + 8) * QP + kb + tid4];
                unsigned a2 = su[P_OFF + (w16 + grp)     * QP + kb + tid4 + 4];
                unsigned a3 = su[P_OFF + (w16 + grp + 8) * QP + kb + tid4 + 4];
#pragma unroll
                for (int nt = 0; nt < 8; nt++) {
                    unsigned b0 = su[V_OFF + (kb + tid4)     * VP + nt * 8 + grp];
                    unsigned b1 = su[V_OFF + (kb + tid4 + 4) * VP + nt * 8 + grp];
                    MMA_TF32(oacc[nt], a0, a1, a2, a3, b0, b1);
                }
            }
        }
        __syncthreads();   // before next K/V overwrite
    }

    // epilogue: normalize, write y[b, row, h*64 + col]
    float inv0 = 1.0f / lrow[0];
    float inv1 = 1.0f / lrow[1];
    int r0 = q0 + w16 + grp;
    int r1 = r0 + 8;
#pragma unroll
    for (int nt = 0; nt < 8; nt++) {
        int col = h * DD + nt * 8 + 2 * tid4;
        float2 o0 = { oacc[nt][0] * inv0, oacc[nt][1] * inv0 };
        float2 o1 = { oacc[nt][2] * inv1, oacc[nt][3] * inv1 };
        *(float2*)&g_y[((size_t)b * TT + r0) * EE + col] = o0;
        *(float2*)&g_y[((size_t)b * TT + r1) * EE + col] = o1;
    }
}

// ---------------------------------------------------------------------------
extern "C" void kernel_launch(void* const* d_in, const int* in_sizes, int n_in,
                              void* d_out, int out_size)
{
    const float* x      = (const float*)d_in[0];
    const float* W_attn = (const float*)d_in[1];
    const float* b_attn = (const float*)d_in[2];
    const float* W_proj = (const float*)d_in[3];
    const float* b_proj = (const float*)d_in[4];
    float* out = (float*)d_out;

    float *qkv, *y;
    cudaGetSymbolAddress((void**)&qkv, g_qkv);
    cudaGetSymbolAddress((void**)&y, g_y);

    // 1) QKV projection: [8192, 768] @ [768, 2304] + b
    gemm_tf32_kernel<<<dim3(E3 / 128, (BB * TT) / 128), 256>>>(
        x, W_attn, b_attn, qkv, BB * TT, E3, EE);

    // 2) causal flash attention (TF32 MMA), 128-row q tiles
    cudaFuncSetAttribute(attn_tf32_kernel,
                         cudaFuncAttributeMaxDynamicSharedMemorySize, ATTN_SMEM);
    attn_tf32_kernel<<<dim3(TT / 128, BB * HH), 256, ATTN_SMEM>>>();

    // 3) output projection: [8192, 768] @ [768, 768] + b
    gemm_tf32_kernel<<<dim3(EE / 128, (BB * TT) / 128), 256>>>(
        y, W_proj, b_proj, out, BB * TT, EE, EE);
}

// round 6
// speedup vs baseline: 7.2286x; 1.9368x over previous
#include <cuda_runtime.h>
#include <cuda_fp16.h>
#include <cstdint>

#define BB 2
#define TT 4096
#define EE 768
#define HH 12
#define DD 64
#define E3 (3*EE)
#define MTOT (BB*TT)

// Scratch (allocation-free rule: __device__ globals)
__device__ __half g_xh [(size_t)MTOT*EE];   // x in fp16
__device__ __half g_qkv[(size_t)MTOT*E3];   // [B,T,3E] fp16
__device__ __half g_y  [(size_t)MTOT*EE];   // attention out fp16
__device__ __half g_wt1[(size_t)E3*EE];     // W_attn^T [2304][768] fp16 (K-major)
__device__ __half g_wt2[(size_t)EE*EE];     // W_proj^T [768][768]  fp16 (K-major)

// ---------------------------------------------------------------------------
// helpers
// ---------------------------------------------------------------------------
__device__ __forceinline__ uint32_t smem_u32(const void* p) {
    uint32_t a;
    asm("{ .reg .u64 t; cvta.to.shared.u64 t, %1; cvt.u32.u64 %0, t; }" : "=r"(a) : "l"(p));
    return a;
}
__device__ __forceinline__ void cp16(uint32_t saddr, const void* g) {
    asm volatile("cp.async.cg.shared.global [%0], [%1], 16;" :: "r"(saddr), "l"(g));
}
#define CP_COMMIT() asm volatile("cp.async.commit_group;" ::: "memory")
#define CP_WAIT0()  asm volatile("cp.async.wait_group 0;" ::: "memory")
#define CP_WAIT1()  asm volatile("cp.async.wait_group 1;" ::: "memory")

__device__ __forceinline__ unsigned h2bits(__half2 h) { return *(unsigned*)&h; }
__device__ __forceinline__ unsigned packf(float a, float b) {
    __half2 h = __floats2half2_rn(a, b);
    return *(unsigned*)&h;
}
__device__ __forceinline__ unsigned packh(__half a, __half b) {
    __half2 h = __halves2half2(a, b);
    return *(unsigned*)&h;
}

#define MMA_F16(c, a0, a1, a2, a3, b0, b1)                                    \
    asm volatile(                                                             \
        "mma.sync.aligned.m16n8k16.row.col.f32.f16.f16.f32 "                  \
        "{%0,%1,%2,%3},{%4,%5,%6,%7},{%8,%9},{%0,%1,%2,%3};"                  \
        : "+f"((c)[0]), "+f"((c)[1]), "+f"((c)[2]), "+f"((c)[3])              \
        : "r"(a0), "r"(a1), "r"(a2), "r"(a3), "r"(b0), "r"(b1))

// ---------------------------------------------------------------------------
// aux: fp32 -> fp16 convert (x), and W[K][N] fp32 -> Wt[N][K] fp16
// ---------------------------------------------------------------------------
__global__ void f2h_kernel(const float* __restrict__ in, __half* __restrict__ out, int n)
{
    int i = (blockIdx.x * blockDim.x + threadIdx.x) * 4;
    if (i >= n) return;
    float4 v = *(const float4*)(in + i);
    uint2 u = { packf(v.x, v.y), packf(v.z, v.w) };
    *(uint2*)(out + i) = u;
}

__global__ void transpose_h(const float* __restrict__ W, __half* __restrict__ Wt,
                            int K, int N)
{
    __shared__ __half t[32][33];
    const int n0 = blockIdx.x * 32, k0 = blockIdx.y * 32;
    const int tx = threadIdx.x, ty = threadIdx.y;   // 32 x 8
#pragma unroll
    for (int i = 0; i < 32; i += 8)
        t[ty + i][tx] = __float2half(W[(size_t)(k0 + ty + i) * N + n0 + tx]);
    __syncthreads();
#pragma unroll
    for (int i = 0; i < 32; i += 8)
        Wt[(size_t)(n0 + ty + i) * K + k0 + tx] = t[tx][ty + i];
}

// ---------------------------------------------------------------------------
// FP16 GEMM: C[M,N] = A[M,K] @ Wt[N,K]^T + bias
// 128x128 tile, BK=64, 2-stage cp.async double buffer, 256 threads (8 warps),
// warp tile 32x64. smem pitch 72 halves (144 B: 16B-aligned rows, word-stride
// 36 == 4 mod 32 -> conflict-free fragment LDS).
// ---------------------------------------------------------------------------
#define GP 72
#define GA(s) ((s) * 9216)             // A stage offset (halves)
#define GB(s) (18432 + (s) * 9216)     // B stage offset (halves)
#define GEMM_SMEM (36864 * 2)          // 73728 B

template<int HALF_OUT>
__global__ __launch_bounds__(256, 2) void gemm_f16(
    const __half* __restrict__ A, const __half* __restrict__ Bt,
    const float* __restrict__ bias, void* __restrict__ Cv,
    int M, int N, int K)
{
    extern __shared__ __half sh[];
    const uint32_t sbase = smem_u32(sh);
    const int tid  = threadIdx.x;
    const int lane = tid & 31;
    const int warp = tid >> 5;
    const int grp  = lane >> 2;
    const int tid4 = lane & 3;
    const int wm = warp & 3;
    const int wn = warp >> 2;
    const int rowBase = blockIdx.y * 128;
    const int colBase = blockIdx.x * 128;

    float acc[2][8][4];
#pragma unroll
    for (int mt = 0; mt < 2; mt++)
#pragma unroll
        for (int nt = 0; nt < 8; nt++)
#pragma unroll
            for (int c = 0; c < 4; c++) acc[mt][nt][c] = 0.f;

    const int nc = K / 64;

    // prefetch chunk 0
    {
#pragma unroll
        for (int i = 0; i < 4; i++) {
            int idx = tid + 256 * i;
            int m = idx >> 3, kc = (idx & 7) * 8;
            cp16(sbase + (GA(0) + m * GP + kc) * 2, A  + (size_t)(rowBase + m) * K + kc);
            cp16(sbase + (GB(0) + m * GP + kc) * 2, Bt + (size_t)(colBase + m) * K + kc);
        }
        CP_COMMIT();
    }

    for (int c = 0; c < nc; c++) {
        const int s = c & 1;
        if (c + 1 < nc) {
            const int s1 = s ^ 1;
            const int k0 = (c + 1) * 64;
#pragma unroll
            for (int i = 0; i < 4; i++) {
                int idx = tid + 256 * i;
                int m = idx >> 3, kc = (idx & 7) * 8;
                cp16(sbase + (GA(s1) + m * GP + kc) * 2, A  + (size_t)(rowBase + m) * K + k0 + kc);
                cp16(sbase + (GB(s1) + m * GP + kc) * 2, Bt + (size_t)(colBase + m) * K + k0 + kc);
            }
            CP_COMMIT();
            CP_WAIT1();
        } else {
            CP_WAIT0();
        }
        __syncthreads();

        const __half* As = sh + GA(s);
        const __half* Bs = sh + GB(s);
#pragma unroll
        for (int kb = 0; kb < 64; kb += 16) {
            unsigned a[2][4];
#pragma unroll
            for (int mt = 0; mt < 2; mt++) {
                int r = wm * 32 + mt * 16 + grp;
                a[mt][0] = *(const unsigned*)&As[(r)     * GP + kb + 2 * tid4];
                a[mt][1] = *(const unsigned*)&As[(r + 8) * GP + kb + 2 * tid4];
                a[mt][2] = *(const unsigned*)&As[(r)     * GP + kb + 2 * tid4 + 8];
                a[mt][3] = *(const unsigned*)&As[(r + 8) * GP + kb + 2 * tid4 + 8];
            }
#pragma unroll
            for (int nt = 0; nt < 8; nt++) {
                int nr = wn * 64 + nt * 8 + grp;
                unsigned b0 = *(const unsigned*)&Bs[nr * GP + kb + 2 * tid4];
                unsigned b1 = *(const unsigned*)&Bs[nr * GP + kb + 2 * tid4 + 8];
                MMA_F16(acc[0][nt], a[0][0], a[0][1], a[0][2], a[0][3], b0, b1);
                MMA_F16(acc[1][nt], a[1][0], a[1][1], a[1][2], a[1][3], b0, b1);
            }
        }
        __syncthreads();
    }

    // epilogue: + bias
#pragma unroll
    for (int mt = 0; mt < 2; mt++) {
        int r0 = rowBase + wm * 32 + mt * 16 + grp;
        int r1 = r0 + 8;
#pragma unroll
        for (int nt = 0; nt < 8; nt++) {
            int col = colBase + wn * 64 + nt * 8 + 2 * tid4;
            float bx = bias[col], by = bias[col + 1];
            if (HALF_OUT) {
                __half* C = (__half*)Cv;
                *(unsigned*)&C[(size_t)r0 * N + col] = packf(acc[mt][nt][0] + bx, acc[mt][nt][1] + by);
                *(unsigned*)&C[(size_t)r1 * N + col] = packf(acc[mt][nt][2] + bx, acc[mt][nt][3] + by);
            } else {
                float* C = (float*)Cv;
                float2 o0 = { acc[mt][nt][0] + bx, acc[mt][nt][1] + by };
                float2 o1 = { acc[mt][nt][2] + bx, acc[mt][nt][3] + by };
                *(float2*)&C[(size_t)r0 * N + col] = o0;
                *(float2*)&C[(size_t)r1 * N + col] = o1;
            }
        }
    }
}

// ---------------------------------------------------------------------------
// Flash attention, FP16 mma (m16n8k16), register-resident P.
// Block = (b, h, 128-row q tile). 256 threads = 8 warps, warp owns 16 q rows.
// K/V double-buffered via cp.async. Pitch 72 halves (144 B rows).
// ---------------------------------------------------------------------------
#define AQ 0
#define AK(s) (9216 + (s) * 4608)
#define AV(s) (18432 + (s) * 4608)
#define ATTN_SMEM (27648 * 2)          // 55296 B

__global__ __launch_bounds__(256, 2) void attn_f16_kernel()
{
    extern __shared__ __half sh[];
    const uint32_t sbase = smem_u32(sh);

    const int tid  = threadIdx.x;
    const int lane = tid & 31;
    const int warp = tid >> 5;
    const int grp  = lane >> 2;
    const int tid4 = lane & 3;
    const int w16  = warp * 16;

    const int qt = blockIdx.x;
    const int bh = blockIdx.y;
    const int b = bh / HH, h = bh % HH;
    const int q0 = qt * 128;

    const size_t base = (size_t)b * TT * E3 + (size_t)h * DD;  // half elements

    // load Q tile (128x64 halves), scale 0.125 folded in
    const __half2 sc2 = __half2half2(__float2half(0.125f));
#pragma unroll
    for (int i = tid; i < 2048; i += 256) {
        int r = i >> 4, c4 = (i & 15) * 4;
        uint2 u = *(const uint2*)&g_qkv[base + (size_t)(q0 + r) * E3 + c4];
        __half2 h0 = __hmul2(*(__half2*)&u.x, sc2);
        __half2 h1 = __hmul2(*(__half2*)&u.y, sc2);
        uint2 o = { h2bits(h0), h2bits(h1) };
        *(uint2*)&sh[AQ + r * GP + c4] = o;
    }

    float oacc[8][4];
    float mrow[2] = { -1e30f, -1e30f };
    float lrow[2] = { 0.f, 0.f };
#pragma unroll
    for (int nt = 0; nt < 8; nt++)
#pragma unroll
        for (int c = 0; c < 4; c++) oacc[nt][c] = 0.f;

    const int njt = 2 * qt + 2;

    // prefetch K/V tile 0
#pragma unroll
    for (int i = 0; i < 2; i++) {
        int idx = tid + 256 * i;
        int r = idx >> 3, c16 = (idx & 7) * 8;
        const __half* gk = &g_qkv[base + (size_t)r * E3 + EE + c16];
        const __half* gv = &g_qkv[base + (size_t)r * E3 + 2 * EE + c16];
        cp16(sbase + (AK(0) + r * GP + c16) * 2, gk);
        cp16(sbase + (AV(0) + r * GP + c16) * 2, gv);
    }
    CP_COMMIT();

    for (int jt = 0; jt < njt; jt++) {
        const int k0 = jt * 64;
        const int s = jt & 1;
        if (jt + 1 < njt) {
            const int s1 = s ^ 1;
            const int kn = (jt + 1) * 64;
#pragma unroll
            for (int i = 0; i < 2; i++) {
                int idx = tid + 256 * i;
                int r = idx >> 3, c16 = (idx & 7) * 8;
                const __half* gk = &g_qkv[base + (size_t)(kn + r) * E3 + EE + c16];
                const __half* gv = &g_qkv[base + (size_t)(kn + r) * E3 + 2 * EE + c16];
                cp16(sbase + (AK(s1) + r * GP + c16) * 2, gk);
                cp16(sbase + (AV(s1) + r * GP + c16) * 2, gv);
            }
            CP_COMMIT();
            CP_WAIT1();
        } else {
            CP_WAIT0();
        }
        __syncthreads();

        const bool active = (k0 <= q0 + w16 + 15);
        if (active) {
            const __half* Ks = sh + AK(s);
            const __half* Vs = sh + AV(s);

            // ---- S = Q K^T  (warp: 16 x 64) ----
            float sacc[8][4];
#pragma unroll
            for (int nt = 0; nt < 8; nt++)
#pragma unroll
                for (int c = 0; c < 4; c++) sacc[nt][c] = 0.f;

#pragma unroll
            for (int kb = 0; kb < 64; kb += 16) {
                unsigned a0 = *(const unsigned*)&sh[AQ + (w16 + grp)     * GP + kb + 2 * tid4];
                unsigned a1 = *(const unsigned*)&sh[AQ + (w16 + grp + 8) * GP + kb + 2 * tid4];
                unsigned a2 = *(const unsigned*)&sh[AQ + (w16 + grp)     * GP + kb + 2 * tid4 + 8];
                unsigned a3 = *(const unsigned*)&sh[AQ + (w16 + grp + 8) * GP + kb + 2 * tid4 + 8];
#pragma unroll
                for (int nt = 0; nt < 8; nt++) {
                    unsigned b0 = *(const unsigned*)&Ks[(nt * 8 + grp) * GP + kb + 2 * tid4];
                    unsigned b1 = *(const unsigned*)&Ks[(nt * 8 + grp) * GP + kb + 2 * tid4 + 8];
                    MMA_F16(sacc[nt], a0, a1, a2, a3, b0, b1);
                }
            }

            // causal mask
            if (k0 + 63 > q0 + w16) {
#pragma unroll
                for (int nt = 0; nt < 8; nt++)
#pragma unroll
                    for (int c = 0; c < 4; c++) {
                        int row = q0 + w16 + grp + 8 * (c >> 1);
                        int col = k0 + nt * 8 + 2 * tid4 + (c & 1);
                        if (col > row) sacc[nt][c] = -1e30f;
                    }
            }

            // ---- online softmax; P packed to registers as fp16 ----
            unsigned pr[8][2];
#pragma unroll
            for (int p = 0; p < 2; p++) {
                float mx = -1e30f;
#pragma unroll
                for (int nt = 0; nt < 8; nt++)
                    mx = fmaxf(mx, fmaxf(sacc[nt][2 * p], sacc[nt][2 * p + 1]));
                mx = fmaxf(mx, __shfl_xor_sync(0xffffffffu, mx, 1));
                mx = fmaxf(mx, __shfl_xor_sync(0xffffffffu, mx, 2));
                float mnew = fmaxf(mrow[p], mx);
                float alpha = __expf(mrow[p] - mnew);
                mrow[p] = mnew;
                float sum = 0.f;
#pragma unroll
                for (int nt = 0; nt < 8; nt++) {
                    float p0 = __expf(sacc[nt][2 * p]     - mnew);
                    float p1 = __expf(sacc[nt][2 * p + 1] - mnew);
                    sum += p0 + p1;
                    pr[nt][p] = packf(p0, p1);
                }
                sum += __shfl_xor_sync(0xffffffffu, sum, 1);
                sum += __shfl_xor_sync(0xffffffffu, sum, 2);
                lrow[p] = lrow[p] * alpha + sum;
#pragma unroll
                for (int nt = 0; nt < 8; nt++) {
                    oacc[nt][2 * p]     *= alpha;
                    oacc[nt][2 * p + 1] *= alpha;
                }
            }

            // ---- O += P V : P's C-fragment IS the A-fragment (f16 k16) ----
#pragma unroll
            for (int s4 = 0; s4 < 4; s4++) {
                const int kb = 16 * s4;
                unsigned a0 = pr[2 * s4][0];
                unsigned a1 = pr[2 * s4][1];
                unsigned a2 = pr[2 * s4 + 1][0];
                unsigned a3 = pr[2 * s4 + 1][1];
#pragma unroll
                for (int nt = 0; nt < 8; nt++) {
                    const int nc = nt * 8 + grp;
                    unsigned b0 = packh(Vs[(kb + 2 * tid4)     * GP + nc],
                                        Vs[(kb + 2 * tid4 + 1) * GP + nc]);
                    unsigned b1 = packh(Vs[(kb + 2 * tid4 + 8) * GP + nc],
                                        Vs[(kb + 2 * tid4 + 9) * GP + nc]);
                    MMA_F16(oacc[nt], a0, a1, a2, a3, b0, b1);
                }
            }
        }
        __syncthreads();   // before next K/V overwrite
    }

    // epilogue: normalize, write y (fp16)
    float inv0 = 1.0f / lrow[0];
    float inv1 = 1.0f / lrow[1];
    int r0 = q0 + w16 + grp;
    int r1 = r0 + 8;
#pragma unroll
    for (int nt = 0; nt < 8; nt++) {
        int col = h * DD + nt * 8 + 2 * tid4;
        *(unsigned*)&g_y[((size_t)b * TT + r0) * EE + col] =
            packf(oacc[nt][0] * inv0, oacc[nt][1] * inv0);
        *(unsigned*)&g_y[((size_t)b * TT + r1) * EE + col] =
            packf(oacc[nt][2] * inv1, oacc[nt][3] * inv1);
    }
}

// ---------------------------------------------------------------------------
extern "C" void kernel_launch(void* const* d_in, const int* in_sizes, int n_in,
                              void* d_out, int out_size)
{
    const float* x      = (const float*)d_in[0];
    const float* W_attn = (const float*)d_in[1];
    const float* b_attn = (const float*)d_in[2];
    const float* W_proj = (const float*)d_in[3];
    const float* b_proj = (const float*)d_in[4];
    float* out = (float*)d_out;

    __half *xh, *qkv, *y, *wt1, *wt2;
    cudaGetSymbolAddress((void**)&xh,  g_xh);
    cudaGetSymbolAddress((void**)&qkv, g_qkv);
    cudaGetSymbolAddress((void**)&y,   g_y);
    cudaGetSymbolAddress((void**)&wt1, g_wt1);
    cudaGetSymbolAddress((void**)&wt2, g_wt2);

    cudaFuncSetAttribute(gemm_f16<1>, cudaFuncAttributeMaxDynamicSharedMemorySize, GEMM_SMEM);
    cudaFuncSetAttribute(gemm_f16<0>, cudaFuncAttributeMaxDynamicSharedMemorySize, GEMM_SMEM);
    cudaFuncSetAttribute(attn_f16_kernel, cudaFuncAttributeMaxDynamicSharedMemorySize, ATTN_SMEM);

    // 0) convert x -> fp16; transpose weights -> fp16 K-major
    f2h_kernel<<<(MTOT * EE / 4 + 255) / 256, 256>>>(x, xh, MTOT * EE);
    transpose_h<<<dim3(E3 / 32, EE / 32), dim3(32, 8)>>>(W_attn, wt1, EE, E3);
    transpose_h<<<dim3(EE / 32, EE / 32), dim3(32, 8)>>>(W_proj, wt2, EE, EE);

    // 1) QKV projection: [8192,768] @ [768,2304] + b  -> qkv (fp16)
    gemm_f16<1><<<dim3(E3 / 128, MTOT / 128), 256, GEMM_SMEM>>>(
        xh, wt1, b_attn, qkv, MTOT, E3, EE);

    // 2) causal flash attention (fp16 MMA, register P) -> y (fp16)
    attn_f16_kernel<<<dim3(TT / 128, BB * HH), 256, ATTN_SMEM>>>();

    // 3) output projection: [8192,768] @ [768,768] + b -> out (fp32)
    gemm_f16<0><<<dim3(EE / 128, MTOT / 128), 256, GEMM_SMEM>>>(
        y, wt2, b_proj, out, MTOT, EE, EE);
}

// round 7
// speedup vs baseline: 8.3166x; 1.1505x over previous
#include <cuda_runtime.h>
#include <cuda_fp16.h>
#include <cstdint>

#define BB 2
#define TT 4096
#define EE 768
#define HH 12
#define DD 64
#define E3 (3*EE)
#define MTOT (BB*TT)

// Scratch (allocation-free rule: __device__ globals)
__device__ __half g_xh [(size_t)MTOT*EE];   // x in fp16
__device__ __half g_qkv[(size_t)MTOT*E3];   // [B,T,3E] fp16
__device__ __half g_y  [(size_t)MTOT*EE];   // attention out fp16
__device__ __half g_wt1[(size_t)E3*EE];     // W_attn^T [2304][768] fp16 (K-major)
__device__ __half g_wt2[(size_t)EE*EE];     // W_proj^T [768][768]  fp16 (K-major)

// ---------------------------------------------------------------------------
// helpers
// ---------------------------------------------------------------------------
__device__ __forceinline__ uint32_t smem_u32(const void* p) {
    uint32_t a;
    asm("{ .reg .u64 t; cvta.to.shared.u64 t, %1; cvt.u32.u64 %0, t; }" : "=r"(a) : "l"(p));
    return a;
}
__device__ __forceinline__ void cp16(uint32_t saddr, const void* g) {
    asm volatile("cp.async.cg.shared.global [%0], [%1], 16;" :: "r"(saddr), "l"(g));
}
#define CP_COMMIT() asm volatile("cp.async.commit_group;" ::: "memory")
#define CP_WAIT0()  asm volatile("cp.async.wait_group 0;" ::: "memory")
#define CP_WAIT1()  asm volatile("cp.async.wait_group 1;" ::: "memory")

__device__ __forceinline__ unsigned h2bits(__half2 h) { return *(unsigned*)&h; }
__device__ __forceinline__ unsigned packf(float a, float b) {
    __half2 h = __floats2half2_rn(a, b);
    return *(unsigned*)&h;
}

__device__ __forceinline__ void ldsm4(uint32_t addr, unsigned* r) {
    asm volatile("ldmatrix.sync.aligned.m8n8.x4.shared.b16 {%0,%1,%2,%3}, [%4];"
        : "=r"(r[0]), "=r"(r[1]), "=r"(r[2]), "=r"(r[3]) : "r"(addr));
}
__device__ __forceinline__ void ldsm4t(uint32_t addr, unsigned* r) {
    asm volatile("ldmatrix.sync.aligned.m8n8.x4.trans.shared.b16 {%0,%1,%2,%3}, [%4];"
        : "=r"(r[0]), "=r"(r[1]), "=r"(r[2]), "=r"(r[3]) : "r"(addr));
}

#define MMA_F16(c, a0, a1, a2, a3, b0, b1)                                    \
    asm volatile(                                                             \
        "mma.sync.aligned.m16n8k16.row.col.f32.f16.f16.f32 "                  \
        "{%0,%1,%2,%3},{%4,%5,%6,%7},{%8,%9},{%0,%1,%2,%3};"                  \
        : "+f"((c)[0]), "+f"((c)[1]), "+f"((c)[2]), "+f"((c)[3])              \
        : "r"(a0), "r"(a1), "r"(a2), "r"(a3), "r"(b0), "r"(b1))

// ---------------------------------------------------------------------------
// aux: fp32 -> fp16 convert (x), and W[K][N] fp32 -> Wt[N][K] fp16
// ---------------------------------------------------------------------------
__global__ void f2h_kernel(const float* __restrict__ in, __half* __restrict__ out, int n)
{
    int i = (blockIdx.x * blockDim.x + threadIdx.x) * 4;
    if (i >= n) return;
    float4 v = *(const float4*)(in + i);
    uint2 u = { packf(v.x, v.y), packf(v.z, v.w) };
    *(uint2*)(out + i) = u;
}

__global__ void transpose_h(const float* __restrict__ W, __half* __restrict__ Wt,
                            int K, int N)
{
    __shared__ __half t[32][33];
    const int n0 = blockIdx.x * 32, k0 = blockIdx.y * 32;
    const int tx = threadIdx.x, ty = threadIdx.y;   // 32 x 8
#pragma unroll
    for (int i = 0; i < 32; i += 8)
        t[ty + i][tx] = __float2half(W[(size_t)(k0 + ty + i) * N + n0 + tx]);
    __syncthreads();
#pragma unroll
    for (int i = 0; i < 32; i += 8)
        Wt[(size_t)(n0 + ty + i) * K + k0 + tx] = t[tx][ty + i];
}

// ---------------------------------------------------------------------------
// FP16 GEMM: C[M,N] = A[M,K] @ Wt[N,K]^T + bias
// 128x128 tile, BK=64, 2-stage cp.async double buffer, 256 threads (8 warps),
// warp tile 32x64. Fragments via ldmatrix.x4. Pitch 72 halves (144 B).
// ---------------------------------------------------------------------------
#define GP 72
#define GA(s) ((s) * 9216)             // A stage offset (halves)
#define GB(s) (18432 + (s) * 9216)     // B stage offset (halves)
#define GEMM_SMEM (36864 * 2)          // 73728 B

template<int HALF_OUT>
__global__ __launch_bounds__(256, 2) void gemm_f16(
    const __half* __restrict__ A, const __half* __restrict__ Bt,
    const float* __restrict__ bias, void* __restrict__ Cv,
    int M, int N, int K)
{
    extern __shared__ __half sh[];
    const uint32_t sbase = smem_u32(sh);
    const int tid  = threadIdx.x;
    const int lane = tid & 31;
    const int warp = tid >> 5;
    const int grp  = lane >> 2;
    const int tid4 = lane & 3;
    const int wm = warp & 3;
    const int wn = warp >> 2;
    const int rowBase = blockIdx.y * 128;
    const int colBase = blockIdx.x * 128;

    // ldmatrix lane addressing (r = row-within-tile, t = tile index)
    const int lr = lane & 7, lt = lane >> 3;
    const uint32_t aoff0 = ((wm * 32 +      (lt & 1) * 8 + lr) * GP + (lt >> 1) * 8) * 2;
    const uint32_t aoff1 = ((wm * 32 + 16 + (lt & 1) * 8 + lr) * GP + (lt >> 1) * 8) * 2;
    const uint32_t boff0 = ((wn * 64 + (lt >> 1) * 8 + lr) * GP + (lt & 1) * 8) * 2;

    float acc[2][8][4];
#pragma unroll
    for (int mt = 0; mt < 2; mt++)
#pragma unroll
        for (int nt = 0; nt < 8; nt++)
#pragma unroll
            for (int c = 0; c < 4; c++) acc[mt][nt][c] = 0.f;

    const int nc = K / 64;

    // prefetch chunk 0
    {
#pragma unroll
        for (int i = 0; i < 4; i++) {
            int idx = tid + 256 * i;
            int m = idx >> 3, kc = (idx & 7) * 8;
            cp16(sbase + (GA(0) + m * GP + kc) * 2, A  + (size_t)(rowBase + m) * K + kc);
            cp16(sbase + (GB(0) + m * GP + kc) * 2, Bt + (size_t)(colBase + m) * K + kc);
        }
        CP_COMMIT();
    }

    for (int c = 0; c < nc; c++) {
        const int s = c & 1;
        if (c + 1 < nc) {
            const int s1 = s ^ 1;
            const int k0 = (c + 1) * 64;
#pragma unroll
            for (int i = 0; i < 4; i++) {
                int idx = tid + 256 * i;
                int m = idx >> 3, kc = (idx & 7) * 8;
                cp16(sbase + (GA(s1) + m * GP + kc) * 2, A  + (size_t)(rowBase + m) * K + k0 + kc);
                cp16(sbase + (GB(s1) + m * GP + kc) * 2, Bt + (size_t)(colBase + m) * K + k0 + kc);
            }
            CP_COMMIT();
            CP_WAIT1();
        } else {
            CP_WAIT0();
        }
        __syncthreads();

        const uint32_t baseA = sbase + GA(s) * 2;
        const uint32_t baseB = sbase + GB(s) * 2;
#pragma unroll
        for (int kb = 0; kb < 64; kb += 16) {
            unsigned a0[4], a1[4];
            ldsm4(baseA + aoff0 + kb * 2, a0);
            ldsm4(baseA + aoff1 + kb * 2, a1);
#pragma unroll
            for (int ntp = 0; ntp < 4; ntp++) {
                unsigned bb[4];
                ldsm4(baseB + boff0 + ntp * (16 * GP * 2) + kb * 2, bb);
                MMA_F16(acc[0][2 * ntp],     a0[0], a0[1], a0[2], a0[3], bb[0], bb[1]);
                MMA_F16(acc[0][2 * ntp + 1], a0[0], a0[1], a0[2], a0[3], bb[2], bb[3]);
                MMA_F16(acc[1][2 * ntp],     a1[0], a1[1], a1[2], a1[3], bb[0], bb[1]);
                MMA_F16(acc[1][2 * ntp + 1], a1[0], a1[1], a1[2], a1[3], bb[2], bb[3]);
            }
        }
        __syncthreads();
    }

    // epilogue: + bias
#pragma unroll
    for (int mt = 0; mt < 2; mt++) {
        int r0 = rowBase + wm * 32 + mt * 16 + grp;
        int r1 = r0 + 8;
#pragma unroll
        for (int nt = 0; nt < 8; nt++) {
            int col = colBase + wn * 64 + nt * 8 + 2 * tid4;
            float bx = bias[col], by = bias[col + 1];
            if (HALF_OUT) {
                __half* C = (__half*)Cv;
                *(unsigned*)&C[(size_t)r0 * N + col] = packf(acc[mt][nt][0] + bx, acc[mt][nt][1] + by);
                *(unsigned*)&C[(size_t)r1 * N + col] = packf(acc[mt][nt][2] + bx, acc[mt][nt][3] + by);
            } else {
                float* C = (float*)Cv;
                float2 o0 = { acc[mt][nt][0] + bx, acc[mt][nt][1] + by };
                float2 o1 = { acc[mt][nt][2] + bx, acc[mt][nt][3] + by };
                *(float2*)&C[(size_t)r0 * N + col] = o0;
                *(float2*)&C[(size_t)r1 * N + col] = o1;
            }
        }
    }
}

// ---------------------------------------------------------------------------
// Flash attention, FP16 mma (m16n8k16), register-resident P,
// fragments via ldmatrix (V via ldmatrix.trans).
// Block = (b, h, 128-row q tile). 256 threads = 8 warps, warp owns 16 q rows.
// ---------------------------------------------------------------------------
#define AQ 0
#define AK(s) (9216 + (s) * 4608)
#define AV(s) (18432 + (s) * 4608)
#define ATTN_SMEM (27648 * 2)          // 55296 B

__global__ __launch_bounds__(256, 2) void attn_f16_kernel()
{
    extern __shared__ __half sh[];
    const uint32_t sbase = smem_u32(sh);

    const int tid  = threadIdx.x;
    const int lane = tid & 31;
    const int warp = tid >> 5;
    const int grp  = lane >> 2;
    const int tid4 = lane & 3;
    const int w16  = warp * 16;

    const int qt = blockIdx.x;
    const int bh = blockIdx.y;
    const int b = bh / HH, h = bh % HH;
    const int q0 = qt * 128;

    const size_t base = (size_t)b * TT * E3 + (size_t)h * DD;  // half elements

    // ldmatrix lane addressing
    const int lr = lane & 7, lt = lane >> 3;
    const uint32_t qoff  = ((w16 + (lt & 1) * 8 + lr) * GP + (lt >> 1) * 8) * 2;
    const uint32_t koff0 = (((lt >> 1) * 8 + lr) * GP + (lt & 1) * 8) * 2;
    const uint32_t voff0 = (((lt & 1) * 8 + lr) * GP + (lt >> 1) * 8) * 2;

    // load Q tile (128x64 halves), scale 0.125 folded in
    const __half2 sc2 = __half2half2(__float2half(0.125f));
#pragma unroll
    for (int i = tid; i < 2048; i += 256) {
        int r = i >> 4, c4 = (i & 15) * 4;
        uint2 u = *(const uint2*)&g_qkv[base + (size_t)(q0 + r) * E3 + c4];
        __half2 h0 = __hmul2(*(__half2*)&u.x, sc2);
        __half2 h1 = __hmul2(*(__half2*)&u.y, sc2);
        uint2 o = { h2bits(h0), h2bits(h1) };
        *(uint2*)&sh[AQ + r * GP + c4] = o;
    }

    float oacc[8][4];
    float mrow[2] = { -1e30f, -1e30f };
    float lrow[2] = { 0.f, 0.f };
#pragma unroll
    for (int nt = 0; nt < 8; nt++)
#pragma unroll
        for (int c = 0; c < 4; c++) oacc[nt][c] = 0.f;

    const int njt = 2 * qt + 2;

    // prefetch K/V tile 0
#pragma unroll
    for (int i = 0; i < 2; i++) {
        int idx = tid + 256 * i;
        int r = idx >> 3, c16 = (idx & 7) * 8;
        cp16(sbase + (AK(0) + r * GP + c16) * 2, &g_qkv[base + (size_t)r * E3 + EE + c16]);
        cp16(sbase + (AV(0) + r * GP + c16) * 2, &g_qkv[base + (size_t)r * E3 + 2 * EE + c16]);
    }
    CP_COMMIT();

    for (int jt = 0; jt < njt; jt++) {
        const int k0 = jt * 64;
        const int s = jt & 1;
        if (jt + 1 < njt) {
            const int s1 = s ^ 1;
            const int kn = (jt + 1) * 64;
#pragma unroll
            for (int i = 0; i < 2; i++) {
                int idx = tid + 256 * i;
                int r = idx >> 3, c16 = (idx & 7) * 8;
                cp16(sbase + (AK(s1) + r * GP + c16) * 2, &g_qkv[base + (size_t)(kn + r) * E3 + EE + c16]);
                cp16(sbase + (AV(s1) + r * GP + c16) * 2, &g_qkv[base + (size_t)(kn + r) * E3 + 2 * EE + c16]);
            }
            CP_COMMIT();
            CP_WAIT1();
        } else {
            CP_WAIT0();
        }
        __syncthreads();

        const bool active = (k0 <= q0 + w16 + 15);
        if (active) {
            const uint32_t baseQ = sbase;             // AQ = 0
            const uint32_t baseK = sbase + AK(s) * 2;
            const uint32_t baseV = sbase + AV(s) * 2;

            // ---- S = Q K^T  (warp: 16 x 64) ----
            float sacc[8][4];
#pragma unroll
            for (int nt = 0; nt < 8; nt++)
#pragma unroll
                for (int c = 0; c < 4; c++) sacc[nt][c] = 0.f;

#pragma unroll
            for (int kb = 0; kb < 64; kb += 16) {
                unsigned qa[4];
                ldsm4(baseQ + qoff + kb * 2, qa);
#pragma unroll
                for (int ntp = 0; ntp < 4; ntp++) {
                    unsigned bb[4];
                    ldsm4(baseK + koff0 + ntp * (16 * GP * 2) + kb * 2, bb);
                    MMA_F16(sacc[2 * ntp],     qa[0], qa[1], qa[2], qa[3], bb[0], bb[1]);
                    MMA_F16(sacc[2 * ntp + 1], qa[0], qa[1], qa[2], qa[3], bb[2], bb[3]);
                }
            }

            // causal mask
            if (k0 + 63 > q0 + w16) {
#pragma unroll
                for (int nt = 0; nt < 8; nt++)
#pragma unroll
                    for (int c = 0; c < 4; c++) {
                        int row = q0 + w16 + grp + 8 * (c >> 1);
                        int col = k0 + nt * 8 + 2 * tid4 + (c & 1);
                        if (col > row) sacc[nt][c] = -1e30f;
                    }
            }

            // ---- online softmax; P packed to registers as fp16 ----
            unsigned pr[8][2];
#pragma unroll
            for (int p = 0; p < 2; p++) {
                float mx = -1e30f;
#pragma unroll
                for (int nt = 0; nt < 8; nt++)
                    mx = fmaxf(mx, fmaxf(sacc[nt][2 * p], sacc[nt][2 * p + 1]));
                mx = fmaxf(mx, __shfl_xor_sync(0xffffffffu, mx, 1));
                mx = fmaxf(mx, __shfl_xor_sync(0xffffffffu, mx, 2));
                float mnew = fmaxf(mrow[p], mx);
                float alpha = __expf(mrow[p] - mnew);
                mrow[p] = mnew;
                float sum = 0.f;
#pragma unroll
                for (int nt = 0; nt < 8; nt++) {
                    float p0 = __expf(sacc[nt][2 * p]     - mnew);
                    float p1 = __expf(sacc[nt][2 * p + 1] - mnew);
                    sum += p0 + p1;
                    pr[nt][p] = packf(p0, p1);
                }
                sum += __shfl_xor_sync(0xffffffffu, sum, 1);
                sum += __shfl_xor_sync(0xffffffffu, sum, 2);
                lrow[p] = lrow[p] * alpha + sum;
#pragma unroll
                for (int nt = 0; nt < 8; nt++) {
                    oacc[nt][2 * p]     *= alpha;
                    oacc[nt][2 * p + 1] *= alpha;
                }
            }

            // ---- O += P V : P's C-fragment IS the A-fragment; V via ldsm.trans ----
#pragma unroll
            for (int s4 = 0; s4 < 4; s4++) {
                unsigned a0 = pr[2 * s4][0];
                unsigned a1 = pr[2 * s4][1];
                unsigned a2 = pr[2 * s4 + 1][0];
                unsigned a3 = pr[2 * s4 + 1][1];
#pragma unroll
                for (int ntp = 0; ntp < 4; ntp++) {
                    unsigned bb[4];
                    ldsm4t(baseV + voff0 + s4 * (16 * GP * 2) + ntp * 32, bb);
                    MMA_F16(oacc[2 * ntp],     a0, a1, a2, a3, bb[0], bb[1]);
                    MMA_F16(oacc[2 * ntp + 1], a0, a1, a2, a3, bb[2], bb[3]);
                }
            }
        }
        __syncthreads();   // before next K/V overwrite
    }

    // epilogue: normalize, write y (fp16)
    float inv0 = 1.0f / lrow[0];
    float inv1 = 1.0f / lrow[1];
    int r0 = q0 + w16 + grp;
    int r1 = r0 + 8;
#pragma unroll
    for (int nt = 0; nt < 8; nt++) {
        int col = h * DD + nt * 8 + 2 * tid4;
        *(unsigned*)&g_y[((size_t)b * TT + r0) * EE + col] =
            packf(oacc[nt][0] * inv0, oacc[nt][1] * inv0);
        *(unsigned*)&g_y[((size_t)b * TT + r1) * EE + col] =
            packf(oacc[nt][2] * inv1, oacc[nt][3] * inv1);
    }
}

// ---------------------------------------------------------------------------
extern "C" void kernel_launch(void* const* d_in, const int* in_sizes, int n_in,
                              void* d_out, int out_size)
{
    const float* x      = (const float*)d_in[0];
    const float* W_attn = (const float*)d_in[1];
    const float* b_attn = (const float*)d_in[2];
    const float* W_proj = (const float*)d_in[3];
    const float* b_proj = (const float*)d_in[4];
    float* out = (float*)d_out;

    __half *xh, *qkv, *y, *wt1, *wt2;
    cudaGetSymbolAddress((void**)&xh,  g_xh);
    cudaGetSymbolAddress((void**)&qkv, g_qkv);
    cudaGetSymbolAddress((void**)&y,   g_y);
    cudaGetSymbolAddress((void**)&wt1, g_wt1);
    cudaGetSymbolAddress((void**)&wt2, g_wt2);

    cudaFuncSetAttribute(gemm_f16<1>, cudaFuncAttributeMaxDynamicSharedMemorySize, GEMM_SMEM);
    cudaFuncSetAttribute(gemm_f16<0>, cudaFuncAttributeMaxDynamicSharedMemorySize, GEMM_SMEM);
    cudaFuncSetAttribute(attn_f16_kernel, cudaFuncAttributeMaxDynamicSharedMemorySize, ATTN_SMEM);

    // 0) convert x -> fp16; transpose weights -> fp16 K-major
    f2h_kernel<<<(MTOT * EE / 4 + 255) / 256, 256>>>(x, xh, MTOT * EE);
    transpose_h<<<dim3(E3 / 32, EE / 32), dim3(32, 8)>>>(W_attn, wt1, EE, E3);
    transpose_h<<<dim3(EE / 32, EE / 32), dim3(32, 8)>>>(W_proj, wt2, EE, EE);

    // 1) QKV projection: [8192,768] @ [768,2304] + b  -> qkv (fp16)
    gemm_f16<1><<<dim3(E3 / 128, MTOT / 128), 256, GEMM_SMEM>>>(
        xh, wt1, b_attn, qkv, MTOT, E3, EE);

    // 2) causal flash attention (fp16 MMA, register P, ldmatrix) -> y (fp16)
    attn_f16_kernel<<<dim3(TT / 128, BB * HH), 256, ATTN_SMEM>>>();

    // 3) output projection: [8192,768] @ [768,768] + b -> out (fp32)
    gemm_f16<0><<<dim3(EE / 128, MTOT / 128), 256, GEMM_SMEM>>>(
        y, wt2, b_proj, out, MTOT, EE, EE);
}

// round 8
// speedup vs baseline: 8.4358x; 1.0143x over previous
#include <cuda_runtime.h>
#include <cuda_fp16.h>
#include <cstdint>

#define BB 2
#define TT 4096
#define EE 768
#define HH 12
#define DD 64
#define E3 (3*EE)
#define MTOT (BB*TT)

// Scratch (allocation-free rule: __device__ globals)
__device__ __half g_xh [(size_t)MTOT*EE];   // x in fp16
__device__ __half g_qkv[(size_t)MTOT*E3];   // [B,T,3E] fp16
__device__ __half g_y  [(size_t)MTOT*EE];   // attention out fp16
__device__ __half g_wt1[(size_t)E3*EE];     // W_attn^T [2304][768] fp16 (K-major)
__device__ __half g_wt2[(size_t)EE*EE];     // W_proj^T [768][768]  fp16 (K-major)

// ---------------------------------------------------------------------------
// helpers
// ---------------------------------------------------------------------------
__device__ __forceinline__ uint32_t smem_u32(const void* p) {
    uint32_t a;
    asm("{ .reg .u64 t; cvta.to.shared.u64 t, %1; cvt.u32.u64 %0, t; }" : "=r"(a) : "l"(p));
    return a;
}
__device__ __forceinline__ void cp16(uint32_t saddr, const void* g) {
    asm volatile("cp.async.cg.shared.global [%0], [%1], 16;" :: "r"(saddr), "l"(g));
}
#define CP_COMMIT() asm volatile("cp.async.commit_group;" ::: "memory")
#define CP_WAIT0()  asm volatile("cp.async.wait_group 0;" ::: "memory")
#define CP_WAIT1()  asm volatile("cp.async.wait_group 1;" ::: "memory")

__device__ __forceinline__ unsigned h2bits(__half2 h) { return *(unsigned*)&h; }
__device__ __forceinline__ unsigned packf(float a, float b) {
    __half2 h = __floats2half2_rn(a, b);
    return *(unsigned*)&h;
}

__device__ __forceinline__ void ldsm4(uint32_t addr, unsigned* r) {
    asm volatile("ldmatrix.sync.aligned.m8n8.x4.shared.b16 {%0,%1,%2,%3}, [%4];"
        : "=r"(r[0]), "=r"(r[1]), "=r"(r[2]), "=r"(r[3]) : "r"(addr));
}
__device__ __forceinline__ void ldsm4t(uint32_t addr, unsigned* r) {
    asm volatile("ldmatrix.sync.aligned.m8n8.x4.trans.shared.b16 {%0,%1,%2,%3}, [%4];"
        : "=r"(r[0]), "=r"(r[1]), "=r"(r[2]), "=r"(r[3]) : "r"(addr));
}

#define MMA_F16(c, a0, a1, a2, a3, b0, b1)                                    \
    asm volatile(                                                             \
        "mma.sync.aligned.m16n8k16.row.col.f32.f16.f16.f32 "                  \
        "{%0,%1,%2,%3},{%4,%5,%6,%7},{%8,%9},{%0,%1,%2,%3};"                  \
        : "+f"((c)[0]), "+f"((c)[1]), "+f"((c)[2]), "+f"((c)[3])              \
        : "r"(a0), "r"(a1), "r"(a2), "r"(a3), "r"(b0), "r"(b1))

// ---------------------------------------------------------------------------
// prep: one launch does x->fp16 and both weight transposes (fp32 -> fp16^T)
// ---------------------------------------------------------------------------
#define NB_F2H 6144              // MTOT*EE/4/256
#define NB_T1  1728              // (E3/32)*(EE/32)
#define NB_T2  576               // (EE/32)*(EE/32)

__global__ void prep_kernel(const float* __restrict__ x,
                            const float* __restrict__ W1,
                            const float* __restrict__ W2,
                            __half* __restrict__ xh,
                            __half* __restrict__ wt1,
                            __half* __restrict__ wt2)
{
    const int bid = blockIdx.x;
    const int tid = threadIdx.x;
    if (bid < NB_F2H) {
        int i = (bid * 256 + tid) * 4;
        float4 v = *(const float4*)(x + i);
        uint2 u = { packf(v.x, v.y), packf(v.z, v.w) };
        *(uint2*)(xh + i) = u;
    } else {
        __shared__ __half t[32][33];
        const float* W; __half* Wt; int N, b;
        if (bid < NB_F2H + NB_T1) { W = W1; Wt = wt1; N = E3; b = bid - NB_F2H; }
        else                      { W = W2; Wt = wt2; N = EE; b = bid - NB_F2H - NB_T1; }
        const int K = EE;
        const int nbx = N / 32;
        const int n0 = (b % nbx) * 32, k0 = (b / nbx) * 32;
        const int tx = tid & 31, ty = tid >> 5;
#pragma unroll
        for (int i = 0; i < 32; i += 8)
            t[ty + i][tx] = __float2half(W[(size_t)(k0 + ty + i) * N + n0 + tx]);
        __syncthreads();
#pragma unroll
        for (int i = 0; i < 32; i += 8)
            Wt[(size_t)(n0 + ty + i) * K + k0 + tx] = t[tx][ty + i];
    }
}

// ---------------------------------------------------------------------------
// FP16 GEMM: C[M,N] = A[M,K] @ Wt[N,K]^T + bias
// 128x128 tile, BK=64, 3-stage cp.async pipeline (1 barrier/iter),
// 256 threads (8 warps), warp tile 32x64, ldmatrix fragments. Pitch 72 halves.
// ---------------------------------------------------------------------------
#define GP 72
#define GA(s) ((s) * 9216)             // A stage offset (halves)
#define GB(s) (27648 + (s) * 9216)     // B stage offset (halves)
#define GEMM_SMEM 110592               // 6 * 9216 halves * 2 B

#define GEMM_FILL(c_, st_) do {                                                        \
    const int k0_ = (c_) * 64;                                                         \
    _Pragma("unroll")                                                                  \
    for (int i_ = 0; i_ < 4; i_++) {                                                   \
        int idx_ = tid + 256 * i_;                                                     \
        int m_ = idx_ >> 3, kc_ = (idx_ & 7) * 8;                                      \
        cp16(sbase + (GA(st_) + m_ * GP + kc_) * 2,                                    \
             A  + (size_t)(rowBase + m_) * K + k0_ + kc_);                             \
        cp16(sbase + (GB(st_) + m_ * GP + kc_) * 2,                                    \
             Bt + (size_t)(colBase + m_) * K + k0_ + kc_);                             \
    }                                                                                  \
    CP_COMMIT();                                                                       \
} while (0)

template<int HALF_OUT>
__global__ __launch_bounds__(256, 2) void gemm_f16(
    const __half* __restrict__ A, const __half* __restrict__ Bt,
    const float* __restrict__ bias, void* __restrict__ Cv,
    int M, int N, int K)
{
    extern __shared__ __half sh[];
    const uint32_t sbase = smem_u32(sh);
    const int tid  = threadIdx.x;
    const int lane = tid & 31;
    const int warp = tid >> 5;
    const int grp  = lane >> 2;
    const int tid4 = lane & 3;
    const int wm = warp & 3;
    const int wn = warp >> 2;
    const int rowBase = blockIdx.y * 128;
    const int colBase = blockIdx.x * 128;

    const int lr = lane & 7, lt = lane >> 3;
    const uint32_t aoff0 = ((wm * 32 +      (lt & 1) * 8 + lr) * GP + (lt >> 1) * 8) * 2;
    const uint32_t aoff1 = ((wm * 32 + 16 + (lt & 1) * 8 + lr) * GP + (lt >> 1) * 8) * 2;
    const uint32_t boff0 = ((wn * 64 + (lt >> 1) * 8 + lr) * GP + (lt & 1) * 8) * 2;

    float acc[2][8][4];
#pragma unroll
    for (int mt = 0; mt < 2; mt++)
#pragma unroll
        for (int nt = 0; nt < 8; nt++)
#pragma unroll
            for (int c = 0; c < 4; c++) acc[mt][nt][c] = 0.f;

    const int nc = K / 64;

    GEMM_FILL(0, 0);
    GEMM_FILL(1, 1);

    for (int c = 0; c < nc; c++) {
        if (c + 2 < nc) CP_WAIT1(); else CP_WAIT0();
        __syncthreads();
        if (c + 2 < nc) GEMM_FILL(c + 2, (c + 2) % 3);

        const int s = c % 3;
        const uint32_t baseA = sbase + GA(s) * 2;
        const uint32_t baseB = sbase + GB(s) * 2;
#pragma unroll
        for (int kb = 0; kb < 64; kb += 16) {
            unsigned a0[4], a1[4];
            ldsm4(baseA + aoff0 + kb * 2, a0);
            ldsm4(baseA + aoff1 + kb * 2, a1);
#pragma unroll
            for (int ntp = 0; ntp < 4; ntp++) {
                unsigned bb[4];
                ldsm4(baseB + boff0 + ntp * (16 * GP * 2) + kb * 2, bb);
                MMA_F16(acc[0][2 * ntp],     a0[0], a0[1], a0[2], a0[3], bb[0], bb[1]);
                MMA_F16(acc[0][2 * ntp + 1], a0[0], a0[1], a0[2], a0[3], bb[2], bb[3]);
                MMA_F16(acc[1][2 * ntp],     a1[0], a1[1], a1[2], a1[3], bb[0], bb[1]);
                MMA_F16(acc[1][2 * ntp + 1], a1[0], a1[1], a1[2], a1[3], bb[2], bb[3]);
            }
        }
    }

    // epilogue: + bias
#pragma unroll
    for (int mt = 0; mt < 2; mt++) {
        int r0 = rowBase + wm * 32 + mt * 16 + grp;
        int r1 = r0 + 8;
#pragma unroll
        for (int nt = 0; nt < 8; nt++) {
            int col = colBase + wn * 64 + nt * 8 + 2 * tid4;
            float bx = bias[col], by = bias[col + 1];
            if (HALF_OUT) {
                __half* C = (__half*)Cv;
                *(unsigned*)&C[(size_t)r0 * N + col] = packf(acc[mt][nt][0] + bx, acc[mt][nt][1] + by);
                *(unsigned*)&C[(size_t)r1 * N + col] = packf(acc[mt][nt][2] + bx, acc[mt][nt][3] + by);
            } else {
                float* C = (float*)Cv;
                float2 o0 = { acc[mt][nt][0] + bx, acc[mt][nt][1] + by };
                float2 o1 = { acc[mt][nt][2] + bx, acc[mt][nt][3] + by };
                *(float2*)&C[(size_t)r0 * N + col] = o0;
                *(float2*)&C[(size_t)r1 * N + col] = o1;
            }
        }
    }
}

// ---------------------------------------------------------------------------
// Flash attention: fp16 MMA, register P, ldmatrix, log2-domain half2 softmax.
// 3-stage cp.async K/V pipeline, 1 barrier per k-tile.
// Block = (b, h, 128-row q tile), 256 threads = 8 warps (16 q rows each).
// ---------------------------------------------------------------------------
#define AKo 9216
#define AVo 23040
#define ATTN_SMEM 73728                // (9216 + 6*4608) halves * 2 B

#define ATTN_FILL(j_, st_) do {                                                        \
    const int kr_ = (j_) * 64;                                                         \
    _Pragma("unroll")                                                                  \
    for (int i_ = 0; i_ < 2; i_++) {                                                   \
        int idx_ = tid + 256 * i_;                                                     \
        int r_ = idx_ >> 3, c16_ = (idx_ & 7) * 8;                                     \
        cp16(sbase + (AKo + (st_) * 4608 + r_ * GP + c16_) * 2,                        \
             &g_qkv[base + (size_t)(kr_ + r_) * E3 + EE + c16_]);                      \
        cp16(sbase + (AVo + (st_) * 4608 + r_ * GP + c16_) * 2,                        \
             &g_qkv[base + (size_t)(kr_ + r_) * E3 + 2 * EE + c16_]);                  \
    }                                                                                  \
    CP_COMMIT();                                                                       \
} while (0)

__global__ __launch_bounds__(256, 2) void attn_f16_kernel()
{
    extern __shared__ __half sh[];
    const uint32_t sbase = smem_u32(sh);

    const int tid  = threadIdx.x;
    const int lane = tid & 31;
    const int warp = tid >> 5;
    const int grp  = lane >> 2;
    const int tid4 = lane & 3;
    const int w16  = warp * 16;

    const int qt = (int)gridDim.x - 1 - (int)blockIdx.x;   // heaviest tiles first
    const int bh = blockIdx.y;
    const int b = bh / HH, h = bh % HH;
    const int q0 = qt * 128;

    const size_t base = (size_t)b * TT * E3 + (size_t)h * DD;

    const int lr = lane & 7, lt = lane >> 3;
    const uint32_t qoff  = ((w16 + (lt & 1) * 8 + lr) * GP + (lt >> 1) * 8) * 2;
    const uint32_t koff0 = (((lt >> 1) * 8 + lr) * GP + (lt & 1) * 8) * 2;
    const uint32_t voff0 = (((lt & 1) * 8 + lr) * GP + (lt >> 1) * 8) * 2;

    // load Q tile (128x64), scale 0.125*log2(e) folded in (log2-domain scores)
    const float SC = 0.125f * 1.4426950408889634f;
#pragma unroll
    for (int i = tid; i < 2048; i += 256) {
        int r = i >> 4, c4 = (i & 15) * 4;
        uint2 u = *(const uint2*)&g_qkv[base + (size_t)(q0 + r) * E3 + c4];
        float2 f0 = __half22float2(*(__half2*)&u.x);
        float2 f1 = __half22float2(*(__half2*)&u.y);
        uint2 o = { packf(f0.x * SC, f0.y * SC), packf(f1.x * SC, f1.y * SC) };
        *(uint2*)&sh[r * GP + c4] = o;
    }

    float oacc[8][4];
    float mrow[2] = { -1e30f, -1e30f };
    float lrow[2] = { 0.f, 0.f };
#pragma unroll
    for (int nt = 0; nt < 8; nt++)
#pragma unroll
        for (int c = 0; c < 4; c++) oacc[nt][c] = 0.f;

    const int njt = 2 * qt + 2;

    ATTN_FILL(0, 0);
    if (njt > 1) ATTN_FILL(1, 1);

    for (int jt = 0; jt < njt; jt++) {
        const int k0 = jt * 64;
        if (jt + 2 < njt) CP_WAIT1(); else CP_WAIT0();
        __syncthreads();
        if (jt + 2 < njt) ATTN_FILL(jt + 2, (jt + 2) % 3);

        const bool active = (k0 <= q0 + w16 + 15);
        if (active) {
            const int st = jt % 3;
            const uint32_t baseQ = sbase;
            const uint32_t baseK = sbase + (AKo + st * 4608) * 2;
            const uint32_t baseV = sbase + (AVo + st * 4608) * 2;

            // ---- S = Q K^T (log2 domain) ----
            float sacc[8][4];
#pragma unroll
            for (int nt = 0; nt < 8; nt++)
#pragma unroll
                for (int c = 0; c < 4; c++) sacc[nt][c] = 0.f;

#pragma unroll
            for (int kb = 0; kb < 64; kb += 16) {
                unsigned qa[4];
                ldsm4(baseQ + qoff + kb * 2, qa);
#pragma unroll
                for (int ntp = 0; ntp < 4; ntp++) {
                    unsigned bb[4];
                    ldsm4(baseK + koff0 + ntp * (16 * GP * 2) + kb * 2, bb);
                    MMA_F16(sacc[2 * ntp],     qa[0], qa[1], qa[2], qa[3], bb[0], bb[1]);
                    MMA_F16(sacc[2 * ntp + 1], qa[0], qa[1], qa[2], qa[3], bb[2], bb[3]);
                }
            }

            // causal mask
            if (k0 + 63 > q0 + w16) {
#pragma unroll
                for (int nt = 0; nt < 8; nt++)
#pragma unroll
                    for (int c = 0; c < 4; c++) {
                        int row = q0 + w16 + grp + 8 * (c >> 1);
                        int col = k0 + nt * 8 + 2 * tid4 + (c & 1);
                        if (col > row) sacc[nt][c] = -1e30f;
                    }
            }

            // ---- online softmax (base 2); P = h2exp2 -> fp16 A-fragments ----
            unsigned pr[8][2];
#pragma unroll
            for (int p = 0; p < 2; p++) {
                float mx = -1e30f;
#pragma unroll
                for (int nt = 0; nt < 8; nt++)
                    mx = fmaxf(mx, fmaxf(sacc[nt][2 * p], sacc[nt][2 * p + 1]));
                mx = fmaxf(mx, __shfl_xor_sync(0xffffffffu, mx, 1));
                mx = fmaxf(mx, __shfl_xor_sync(0xffffffffu, mx, 2));
                float mnew = fmaxf(mrow[p], mx);
                float alpha = exp2f(mrow[p] - mnew);
                mrow[p] = mnew;
                float sum = 0.f;
#pragma unroll
                for (int nt = 0; nt < 8; nt++) {
                    __half2 d = __floats2half2_rn(sacc[nt][2 * p]     - mnew,
                                                  sacc[nt][2 * p + 1] - mnew);
                    __half2 e = h2exp2(d);
                    pr[nt][p] = h2bits(e);
                    float2 ef = __half22float2(e);
                    sum += ef.x + ef.y;
                }
                sum += __shfl_xor_sync(0xffffffffu, sum, 1);
                sum += __shfl_xor_sync(0xffffffffu, sum, 2);
                lrow[p] = lrow[p] * alpha + sum;
#pragma unroll
                for (int nt = 0; nt < 8; nt++) {
                    oacc[nt][2 * p]     *= alpha;
                    oacc[nt][2 * p + 1] *= alpha;
                }
            }

            // ---- O += P V (V via ldmatrix.trans) ----
#pragma unroll
            for (int s4 = 0; s4 < 4; s4++) {
                unsigned a0 = pr[2 * s4][0];
                unsigned a1 = pr[2 * s4][1];
                unsigned a2 = pr[2 * s4 + 1][0];
                unsigned a3 = pr[2 * s4 + 1][1];
#pragma unroll
                for (int ntp = 0; ntp < 4; ntp++) {
                    unsigned bb[4];
                    ldsm4t(baseV + voff0 + s4 * (16 * GP * 2) + ntp * 32, bb);
                    MMA_F16(oacc[2 * ntp],     a0, a1, a2, a3, bb[0], bb[1]);
                    MMA_F16(oacc[2 * ntp + 1], a0, a1, a2, a3, bb[2], bb[3]);
                }
            }
        }
    }

    // epilogue: normalize, write y (fp16)
    float inv0 = 1.0f / lrow[0];
    float inv1 = 1.0f / lrow[1];
    int r0 = q0 + w16 + grp;
    int r1 = r0 + 8;
#pragma unroll
    for (int nt = 0; nt < 8; nt++) {
        int col = h * DD + nt * 8 + 2 * tid4;
        *(unsigned*)&g_y[((size_t)b * TT + r0) * EE + col] =
            packf(oacc[nt][0] * inv0, oacc[nt][1] * inv0);
        *(unsigned*)&g_y[((size_t)b * TT + r1) * EE + col] =
            packf(oacc[nt][2] * inv1, oacc[nt][3] * inv1);
    }
}

// ---------------------------------------------------------------------------
extern "C" void kernel_launch(void* const* d_in, const int* in_sizes, int n_in,
                              void* d_out, int out_size)
{
    const float* x      = (const float*)d_in[0];
    const float* W_attn = (const float*)d_in[1];
    const float* b_attn = (const float*)d_in[2];
    const float* W_proj = (const float*)d_in[3];
    const float* b_proj = (const float*)d_in[4];
    float* out = (float*)d_out;

    __half *xh, *qkv, *y, *wt1, *wt2;
    cudaGetSymbolAddress((void**)&xh,  g_xh);
    cudaGetSymbolAddress((void**)&qkv, g_qkv);
    cudaGetSymbolAddress((void**)&y,   g_y);
    cudaGetSymbolAddress((void**)&wt1, g_wt1);
    cudaGetSymbolAddress((void**)&wt2, g_wt2);

    cudaFuncSetAttribute(gemm_f16<1>, cudaFuncAttributeMaxDynamicSharedMemorySize, GEMM_SMEM);
    cudaFuncSetAttribute(gemm_f16<0>, cudaFuncAttributeMaxDynamicSharedMemorySize, GEMM_SMEM);
    cudaFuncSetAttribute(attn_f16_kernel, cudaFuncAttributeMaxDynamicSharedMemorySize, ATTN_SMEM);

    // 0) prep (one launch): x -> fp16, W_attn/W_proj -> fp16 K-major transpose
    prep_kernel<<<NB_F2H + NB_T1 + NB_T2, 256>>>(x, W_attn, W_proj, xh, wt1, wt2);

    // 1) QKV projection: [8192,768] @ [768,2304] + b  -> qkv (fp16)
    gemm_f16<1><<<dim3(E3 / 128, MTOT / 128), 256, GEMM_SMEM>>>(
        xh, wt1, b_attn, qkv, MTOT, E3, EE);

    // 2) causal flash attention -> y (fp16)
    attn_f16_kernel<<<dim3(TT / 128, BB * HH), 256, ATTN_SMEM>>>();

    // 3) output projection: [8192,768] @ [768,768] + b -> out (fp32)
    gemm_f16<0><<<dim3(EE / 128, MTOT / 128), 256, GEMM_SMEM>>>(
        y, wt2, b_proj, out, MTOT, EE, EE);
}

// round 12
// speedup vs baseline: 8.6178x; 1.0216x over previous
#include <cuda_runtime.h>
#include <cuda_fp16.h>
#include <cstdint>

#define BB 2
#define TT 4096
#define EE 768
#define HH 12
#define DD 64
#define E3 (3*EE)
#define MTOT (BB*TT)

// Scratch (allocation-free rule: __device__ globals)
__device__ __half g_xh [(size_t)MTOT*EE];   // x in fp16
__device__ __half g_qkv[(size_t)MTOT*E3];   // [B,T,3E] fp16
__device__ __half g_y  [(size_t)MTOT*EE];   // attention out fp16
__device__ __half g_wt1[(size_t)E3*EE];     // W_attn^T [2304][768] fp16 (K-major)
__device__ __half g_wt2[(size_t)EE*EE];     // W_proj^T [768][768]  fp16 (K-major)

// ---------------------------------------------------------------------------
// helpers
// ---------------------------------------------------------------------------
__device__ __forceinline__ uint32_t smem_u32(const void* p) {
    uint32_t a;
    asm("{ .reg .u64 t; cvta.to.shared.u64 t, %1; cvt.u32.u64 %0, t; }" : "=r"(a) : "l"(p));
    return a;
}
__device__ __forceinline__ void cp16(uint32_t saddr, const void* g) {
    asm volatile("cp.async.cg.shared.global [%0], [%1], 16;" :: "r"(saddr), "l"(g));
}
#define CP_COMMIT() asm volatile("cp.async.commit_group;" ::: "memory")
#define CP_WAIT0()  asm volatile("cp.async.wait_group 0;" ::: "memory")
#define CP_WAIT1()  asm volatile("cp.async.wait_group 1;" ::: "memory")

__device__ __forceinline__ unsigned h2bits(__half2 h) { return *(unsigned*)&h; }
__device__ __forceinline__ unsigned packf(float a, float b) {
    __half2 h = __floats2half2_rn(a, b);
    return *(unsigned*)&h;
}

__device__ __forceinline__ void ldsm4(uint32_t addr, unsigned* r) {
    asm volatile("ldmatrix.sync.aligned.m8n8.x4.shared.b16 {%0,%1,%2,%3}, [%4];"
        : "=r"(r[0]), "=r"(r[1]), "=r"(r[2]), "=r"(r[3]) : "r"(addr));
}
__device__ __forceinline__ void ldsm4t(uint32_t addr, unsigned* r) {
    asm volatile("ldmatrix.sync.aligned.m8n8.x4.trans.shared.b16 {%0,%1,%2,%3}, [%4];"
        : "=r"(r[0]), "=r"(r[1]), "=r"(r[2]), "=r"(r[3]) : "r"(addr));
}

#define MMA_F16(c, a0, a1, a2, a3, b0, b1)                                    \
    asm volatile(                                                             \
        "mma.sync.aligned.m16n8k16.row.col.f32.f16.f16.f32 "                  \
        "{%0,%1,%2,%3},{%4,%5,%6,%7},{%8,%9},{%0,%1,%2,%3};"                  \
        : "+f"((c)[0]), "+f"((c)[1]), "+f"((c)[2]), "+f"((c)[3])              \
        : "r"(a0), "r"(a1), "r"(a2), "r"(a3), "r"(b0), "r"(b1))

// ---------------------------------------------------------------------------
// prep: one launch does x->fp16 and both weight transposes (fp32 -> fp16^T)
// ---------------------------------------------------------------------------
#define NB_F2H 6144
#define NB_T1  1728
#define NB_T2  576

__global__ void prep_kernel(const float* __restrict__ x,
                            const float* __restrict__ W1,
                            const float* __restrict__ W2,
                            __half* __restrict__ xh,
                            __half* __restrict__ wt1,
                            __half* __restrict__ wt2)
{
    const int bid = blockIdx.x;
    const int tid = threadIdx.x;
    if (bid < NB_F2H) {
        int i = (bid * 256 + tid) * 4;
        float4 v = *(const float4*)(x + i);
        uint2 u = { packf(v.x, v.y), packf(v.z, v.w) };
        *(uint2*)(xh + i) = u;
    } else {
        __shared__ __half t[32][33];
        const float* W; __half* Wt; int N, b;
        if (bid < NB_F2H + NB_T1) { W = W1; Wt = wt1; N = E3; b = bid - NB_F2H; }
        else                      { W = W2; Wt = wt2; N = EE; b = bid - NB_F2H - NB_T1; }
        const int K = EE;
        const int nbx = N / 32;
        const int n0 = (b % nbx) * 32, k0 = (b / nbx) * 32;
        const int tx = tid & 31, ty = tid >> 5;
#pragma unroll
        for (int i = 0; i < 32; i += 8)
            t[ty + i][tx] = __float2half(W[(size_t)(k0 + ty + i) * N + n0 + tx]);
        __syncthreads();
#pragma unroll
        for (int i = 0; i < 32; i += 8)
            Wt[(size_t)(n0 + ty + i) * K + k0 + tx] = t[tx][ty + i];
    }
}

// ---------------------------------------------------------------------------
// FP16 GEMM: C[M,N] = A[M,K] @ Wt[N,K]^T + bias
// 128x128 tile, BK=64, 3-stage cp.async pipeline, fragment software pipeline:
// B frags in 3-slot ring (prefetch +2), A frags double-buffered per kb.
// ---------------------------------------------------------------------------
#define GP 72
#define GA(s) ((s) * 9216)
#define GB(s) (27648 + (s) * 9216)
#define GEMM_SMEM 110592

#define GEMM_FILL(c_, st_) do {                                                        \
    const int k0_ = (c_) * 64;                                                         \
    _Pragma("unroll")                                                                  \
    for (int i_ = 0; i_ < 4; i_++) {                                                   \
        int idx_ = tid + 256 * i_;                                                     \
        int m_ = idx_ >> 3, kc_ = (idx_ & 7) * 8;                                      \
        cp16(sbase + (GA(st_) + m_ * GP + kc_) * 2,                                    \
             A  + (size_t)(rowBase + m_) * K + k0_ + kc_);                             \
        cp16(sbase + (GB(st_) + m_ * GP + kc_) * 2,                                    \
             Bt + (size_t)(colBase + m_) * K + k0_ + kc_);                             \
    }                                                                                  \
    CP_COMMIT();                                                                       \
} while (0)

template<int HALF_OUT>
__global__ __launch_bounds__(256, 2) void gemm_f16(
    const __half* __restrict__ A, const __half* __restrict__ Bt,
    const float* __restrict__ bias, void* __restrict__ Cv,
    int M, int N, int K)
{
    extern __shared__ __half sh[];
    const uint32_t sbase = smem_u32(sh);
    const int tid  = threadIdx.x;
    const int lane = tid & 31;
    const int warp = tid >> 5;
    const int grp  = lane >> 2;
    const int tid4 = lane & 3;
    const int wm = warp & 3;
    const int wn = warp >> 2;
    const int rowBase = blockIdx.y * 128;
    const int colBase = blockIdx.x * 128;

    const int lr = lane & 7, lt = lane >> 3;
    const uint32_t aoff0 = ((wm * 32 +      (lt & 1) * 8 + lr) * GP + (lt >> 1) * 8) * 2;
    const uint32_t aoff1 = ((wm * 32 + 16 + (lt & 1) * 8 + lr) * GP + (lt >> 1) * 8) * 2;
    const uint32_t boff0 = ((wn * 64 + (lt >> 1) * 8 + lr) * GP + (lt & 1) * 8) * 2;

    float acc[2][8][4];
#pragma unroll
    for (int mt = 0; mt < 2; mt++)
#pragma unroll
        for (int nt = 0; nt < 8; nt++)
#pragma unroll
            for (int c = 0; c < 4; c++) acc[mt][nt][c] = 0.f;

    const int nc = K / 64;

    GEMM_FILL(0, 0);
    GEMM_FILL(1, 1);

    for (int c = 0; c < nc; c++) {
        if (c + 2 < nc) CP_WAIT1(); else CP_WAIT0();
        __syncthreads();
        if (c + 2 < nc) GEMM_FILL(c + 2, (c + 2) % 3);

        const int s = c % 3;
        const uint32_t baseA = sbase + GA(s) * 2;
        const uint32_t baseB = sbase + GB(s) * 2;

        unsigned afr[2][2][4];
        ldsm4(baseA + aoff0, afr[0][0]);
        ldsm4(baseA + aoff1, afr[0][1]);
        unsigned bb[3][4];
        ldsm4(baseB + boff0,                 bb[0]);
        ldsm4(baseB + boff0 + (16 * GP * 2), bb[1]);

#pragma unroll
        for (int t = 0; t < 16; t++) {
            const int kb = t >> 2, ntp = t & 3, cur = kb & 1;
            if (ntp == 0 && kb < 3) {
                ldsm4(baseA + aoff0 + (kb + 1) * 32, afr[cur ^ 1][0]);
                ldsm4(baseA + aoff1 + (kb + 1) * 32, afr[cur ^ 1][1]);
            }
            if (t + 2 < 16) {
                const int t2 = t + 2;
                ldsm4(baseB + boff0 + (t2 & 3) * (16 * GP * 2) + (t2 >> 2) * 32,
                      bb[t2 % 3]);
            }
            const unsigned* aa0 = afr[cur][0];
            const unsigned* aa1 = afr[cur][1];
            const unsigned* cc  = bb[t % 3];
            MMA_F16(acc[0][2 * ntp],     aa0[0], aa0[1], aa0[2], aa0[3], cc[0], cc[1]);
            MMA_F16(acc[0][2 * ntp + 1], aa0[0], aa0[1], aa0[2], aa0[3], cc[2], cc[3]);
            MMA_F16(acc[1][2 * ntp],     aa1[0], aa1[1], aa1[2], aa1[3], cc[0], cc[1]);
            MMA_F16(acc[1][2 * ntp + 1], aa1[0], aa1[1], aa1[2], aa1[3], cc[2], cc[3]);
        }
    }

    // epilogue: + bias
#pragma unroll
    for (int mt = 0; mt < 2; mt++) {
        int r0 = rowBase + wm * 32 + mt * 16 + grp;
        int r1 = r0 + 8;
#pragma unroll
        for (int nt = 0; nt < 8; nt++) {
            int col = colBase + wn * 64 + nt * 8 + 2 * tid4;
            float bx = bias[col], by = bias[col + 1];
            if (HALF_OUT) {
                __half* C = (__half*)Cv;
                *(unsigned*)&C[(size_t)r0 * N + col] = packf(acc[mt][nt][0] + bx, acc[mt][nt][1] + by);
                *(unsigned*)&C[(size_t)r1 * N + col] = packf(acc[mt][nt][2] + bx, acc[mt][nt][3] + by);
            } else {
                float* C = (float*)Cv;
                float2 o0 = { acc[mt][nt][0] + bx, acc[mt][nt][1] + by };
                float2 o1 = { acc[mt][nt][2] + bx, acc[mt][nt][3] + by };
                *(float2*)&C[(size_t)r0 * N + col] = o0;
                *(float2*)&C[(size_t)r1 * N + col] = o1;
            }
        }
    }
}

// ---------------------------------------------------------------------------
// Flash attention: fp16 MMA, register P, log2-domain half2 softmax,
// Q fragments hoisted to registers, K/V fragment rings (prefetch +2).
// 3-stage cp.async K/V pipeline. 256 threads = 8 warps (16 q rows each).
// ---------------------------------------------------------------------------
#define AKo 9216
#define AVo 23040
#define ATTN_SMEM 73728

#define ATTN_FILL(j_, st_) do {                                                        \
    const int kr_ = (j_) * 64;                                                         \
    _Pragma("unroll")                                                                  \
    for (int i_ = 0; i_ < 2; i_++) {                                                   \
        int idx_ = tid + 256 * i_;                                                     \
        int r_ = idx_ >> 3, c16_ = (idx_ & 7) * 8;                                     \
        cp16(sbase + (AKo + (st_) * 4608 + r_ * GP + c16_) * 2,                        \
             &g_qkv[base + (size_t)(kr_ + r_) * E3 + EE + c16_]);                      \
        cp16(sbase + (AVo + (st_) * 4608 + r_ * GP + c16_) * 2,                        \
             &g_qkv[base + (size_t)(kr_ + r_) * E3 + 2 * EE + c16_]);                  \
    }                                                                                  \
    CP_COMMIT();                                                                       \
} while (0)

__global__ __launch_bounds__(256, 2) void attn_f16_kernel()
{
    extern __shared__ __half sh[];
    const uint32_t sbase = smem_u32(sh);

    const int tid  = threadIdx.x;
    const int lane = tid & 31;
    const int warp = tid >> 5;
    const int grp  = lane >> 2;
    const int tid4 = lane & 3;
    const int w16  = warp * 16;

    const int qt = (int)gridDim.x - 1 - (int)blockIdx.x;   // heaviest tiles first
    const int bh = blockIdx.y;
    const int b = bh / HH, h = bh % HH;
    const int q0 = qt * 128;

    const size_t base = (size_t)b * TT * E3 + (size_t)h * DD;

    const int lr = lane & 7, lt = lane >> 3;
    const uint32_t qoff  = ((w16 + (lt & 1) * 8 + lr) * GP + (lt >> 1) * 8) * 2;
    const uint32_t koff0 = (((lt >> 1) * 8 + lr) * GP + (lt & 1) * 8) * 2;
    const uint32_t voff0 = (((lt & 1) * 8 + lr) * GP + (lt >> 1) * 8) * 2;

    // load Q tile (128x64), scale 0.125*log2(e) folded in (log2-domain scores)
    const float SC = 0.125f * 1.4426950408889634f;
#pragma unroll
    for (int i = tid; i < 2048; i += 256) {
        int r = i >> 4, c4 = (i & 15) * 4;
        uint2 u = *(const uint2*)&g_qkv[base + (size_t)(q0 + r) * E3 + c4];
        float2 f0 = __half22float2(*(__half2*)&u.x);
        float2 f1 = __half22float2(*(__half2*)&u.y);
        uint2 o = { packf(f0.x * SC, f0.y * SC), packf(f1.x * SC, f1.y * SC) };
        *(uint2*)&sh[r * GP + c4] = o;
    }

    const int njt = 2 * qt + 2;
    ATTN_FILL(0, 0);
    if (njt > 1) ATTN_FILL(1, 1);

    __syncthreads();                 // Q stores visible before hoisted ldsm

    // hoist Q fragments: 16 regs, reused for every k tile
    unsigned qfr[4][4];
#pragma unroll
    for (int kb = 0; kb < 4; kb++) ldsm4(sbase + qoff + kb * 32, qfr[kb]);

    float oacc[8][4];
    float mrow[2] = { -1e30f, -1e30f };
    float lrow[2] = { 0.f, 0.f };
#pragma unroll
    for (int nt = 0; nt < 8; nt++)
#pragma unroll
        for (int c = 0; c < 4; c++) oacc[nt][c] = 0.f;

    for (int jt = 0; jt < njt; jt++) {
        const int k0 = jt * 64;
        if (jt + 2 < njt) CP_WAIT1(); else CP_WAIT0();
        __syncthreads();
        if (jt + 2 < njt) ATTN_FILL(jt + 2, (jt + 2) % 3);

        const bool active = (k0 <= q0 + w16 + 15);
        if (active) {
            const int st = jt % 3;
            const uint32_t baseK = sbase + (AKo + st * 4608) * 2;
            const uint32_t baseV = sbase + (AVo + st * 4608) * 2;

            // ---- S = Q K^T (log2 domain), K frags in 3-slot ring ----
            float sacc[8][4];
#pragma unroll
            for (int nt = 0; nt < 8; nt++)
#pragma unroll
                for (int c = 0; c < 4; c++) sacc[nt][c] = 0.f;

            unsigned kf[3][4];
            ldsm4(baseK + koff0,                 kf[0]);
            ldsm4(baseK + koff0 + (16 * GP * 2), kf[1]);
#pragma unroll
            for (int t = 0; t < 16; t++) {
                const int kk = t >> 2, ntp = t & 3;
                if (t + 2 < 16) {
                    const int t2 = t + 2;
                    ldsm4(baseK + koff0 + (t2 & 3) * (16 * GP * 2) + (t2 >> 2) * 32,
                          kf[t2 % 3]);
                }
                const unsigned* q = qfr[kk];
                const unsigned* cc = kf[t % 3];
                MMA_F16(sacc[2 * ntp],     q[0], q[1], q[2], q[3], cc[0], cc[1]);
                MMA_F16(sacc[2 * ntp + 1], q[0], q[1], q[2], q[3], cc[2], cc[3]);
            }

            // causal mask
            if (k0 + 63 > q0 + w16) {
#pragma unroll
                for (int nt = 0; nt < 8; nt++)
#pragma unroll
                    for (int c = 0; c < 4; c++) {
                        int row = q0 + w16 + grp + 8 * (c >> 1);
                        int col = k0 + nt * 8 + 2 * tid4 + (c & 1);
                        if (col > row) sacc[nt][c] = -1e30f;
                    }
            }

            // ---- online softmax (base 2); P = h2exp2 -> fp16 A-fragments ----
            unsigned pr[8][2];
#pragma unroll
            for (int p = 0; p < 2; p++) {
                float mx = -1e30f;
#pragma unroll
                for (int nt = 0; nt < 8; nt++)
                    mx = fmaxf(mx, fmaxf(sacc[nt][2 * p], sacc[nt][2 * p + 1]));
                mx = fmaxf(mx, __shfl_xor_sync(0xffffffffu, mx, 1));
                mx = fmaxf(mx, __shfl_xor_sync(0xffffffffu, mx, 2));
                float mnew = fmaxf(mrow[p], mx);
                float alpha = exp2f(mrow[p] - mnew);
                mrow[p] = mnew;
                float sum = 0.f;
#pragma unroll
                for (int nt = 0; nt < 8; nt++) {
                    __half2 d = __floats2half2_rn(sacc[nt][2 * p]     - mnew,
                                                  sacc[nt][2 * p + 1] - mnew);
                    __half2 e = h2exp2(d);
                    pr[nt][p] = h2bits(e);
                    float2 ef = __half22float2(e);
                    sum += ef.x + ef.y;
                }
                sum += __shfl_xor_sync(0xffffffffu, sum, 1);
                sum += __shfl_xor_sync(0xffffffffu, sum, 2);
                lrow[p] = lrow[p] * alpha + sum;
#pragma unroll
                for (int nt = 0; nt < 8; nt++) {
                    oacc[nt][2 * p]     *= alpha;
                    oacc[nt][2 * p + 1] *= alpha;
                }
            }

            // ---- O += P V (V frags in 3-slot ring via ldmatrix.trans) ----
            unsigned vf[3][4];
            ldsm4t(baseV + voff0,      vf[0]);
            ldsm4t(baseV + voff0 + 32, vf[1]);
#pragma unroll
            for (int t = 0; t < 16; t++) {
                const int s4 = t >> 2, ntp = t & 3;
                if (t + 2 < 16) {
                    const int t2 = t + 2;
                    ldsm4t(baseV + voff0 + (t2 >> 2) * (16 * GP * 2) + (t2 & 3) * 32,
                           vf[t2 % 3]);
                }
                const unsigned* cc = vf[t % 3];
                MMA_F16(oacc[2 * ntp],     pr[2 * s4][0], pr[2 * s4][1],
                        pr[2 * s4 + 1][0], pr[2 * s4 + 1][1], cc[0], cc[1]);
                MMA_F16(oacc[2 * ntp + 1], pr[2 * s4][0], pr[2 * s4][1],
                        pr[2 * s4 + 1][0], pr[2 * s4 + 1][1], cc[2], cc[3]);
            }
        }
    }

    // epilogue: normalize, write y (fp16)
    float inv0 = 1.0f / lrow[0];
    float inv1 = 1.0f / lrow[1];
    int r0 = q0 + w16 + grp;
    int r1 = r0 + 8;
#pragma unroll
    for (int nt = 0; nt < 8; nt++) {
        int col = h * DD + nt * 8 + 2 * tid4;
        *(unsigned*)&g_y[((size_t)b * TT + r0) * EE + col] =
            packf(oacc[nt][0] * inv0, oacc[nt][1] * inv0);
        *(unsigned*)&g_y[((size_t)b * TT + r1) * EE + col] =
            packf(oacc[nt][2] * inv1, oacc[nt][3] * inv1);
    }
}

// ---------------------------------------------------------------------------
extern "C" void kernel_launch(void* const* d_in, const int* in_sizes, int n_in,
                              void* d_out, int out_size)
{
    const float* x      = (const float*)d_in[0];
    const float* W_attn = (const float*)d_in[1];
    const float* b_attn = (const float*)d_in[2];
    const float* W_proj = (const float*)d_in[3];
    const float* b_proj = (const float*)d_in[4];
    float* out = (float*)d_out;

    __half *xh, *qkv, *y, *wt1, *wt2;
    cudaGetSymbolAddress((void**)&xh,  g_xh);
    cudaGetSymbolAddress((void**)&qkv, g_qkv);
    cudaGetSymbolAddress((void**)&y,   g_y);
    cudaGetSymbolAddress((void**)&wt1, g_wt1);
    cudaGetSymbolAddress((void**)&wt2, g_wt2);

    cudaFuncSetAttribute(gemm_f16<1>, cudaFuncAttributeMaxDynamicSharedMemorySize, GEMM_SMEM);
    cudaFuncSetAttribute(gemm_f16<0>, cudaFuncAttributeMaxDynamicSharedMemorySize, GEMM_SMEM);
    cudaFuncSetAttribute(attn_f16_kernel, cudaFuncAttributeMaxDynamicSharedMemorySize, ATTN_SMEM);

    // 0) prep: x -> fp16, weights -> fp16 K-major transpose
    prep_kernel<<<NB_F2H + NB_T1 + NB_T2, 256>>>(x, W_attn, W_proj, xh, wt1, wt2);

    // 1) QKV projection: [8192,768] @ [768,2304] + b  -> qkv (fp16)
    gemm_f16<1><<<dim3(E3 / 128, MTOT / 128), 256, GEMM_SMEM>>>(
        xh, wt1, b_attn, qkv, MTOT, E3, EE);

    // 2) causal flash attention -> y (fp16)
    attn_f16_kernel<<<dim3(TT / 128, BB * HH), 256, ATTN_SMEM>>>();

    // 3) output projection: [8192,768] @ [768,768] + b -> out (fp32)
    gemm_f16<0><<<dim3(EE / 128, MTOT / 128), 256, GEMM_SMEM>>>(
        y, wt2, b_proj, out, MTOT, EE, EE);
}

// round 14
// speedup vs baseline: 8.6855x; 1.0079x over previous
#include <cuda_runtime.h>
#include <cuda_fp16.h>
#include <cstdint>

#define BB 2
#define TT 4096
#define EE 768
#define HH 12
#define DD 64
#define E3 (3*EE)
#define MTOT (BB*TT)

// Scratch (allocation-free rule: __device__ globals)
__device__ __half g_xh [(size_t)MTOT*EE];   // x in fp16
__device__ __half g_qkv[(size_t)MTOT*E3];   // [B,T,3E] fp16
__device__ __half g_y  [(size_t)MTOT*EE];   // attention out fp16
__device__ __half g_wt1[(size_t)E3*EE];     // W_attn^T [2304][768] fp16 (K-major)
__device__ __half g_wt2[(size_t)EE*EE];     // W_proj^T [768][768]  fp16 (K-major)

// ---------------------------------------------------------------------------
// helpers
// ---------------------------------------------------------------------------
__device__ __forceinline__ uint32_t smem_u32(const void* p) {
    uint32_t a;
    asm("{ .reg .u64 t; cvta.to.shared.u64 t, %1; cvt.u32.u64 %0, t; }" : "=r"(a) : "l"(p));
    return a;
}
__device__ __forceinline__ void cp16(uint32_t saddr, const void* g) {
    asm volatile("cp.async.cg.shared.global [%0], [%1], 16;" :: "r"(saddr), "l"(g));
}
#define CP_COMMIT() asm volatile("cp.async.commit_group;" ::: "memory")
#define CP_WAIT0()  asm volatile("cp.async.wait_group 0;" ::: "memory")
#define CP_WAIT1()  asm volatile("cp.async.wait_group 1;" ::: "memory")

__device__ __forceinline__ unsigned h2bits(__half2 h) { return *(unsigned*)&h; }
__device__ __forceinline__ unsigned packf(float a, float b) {
    __half2 h = __floats2half2_rn(a, b);
    return *(unsigned*)&h;
}

__device__ __forceinline__ void ldsm4(uint32_t addr, unsigned* r) {
    asm volatile("ldmatrix.sync.aligned.m8n8.x4.shared.b16 {%0,%1,%2,%3}, [%4];"
        : "=r"(r[0]), "=r"(r[1]), "=r"(r[2]), "=r"(r[3]) : "r"(addr));
}
__device__ __forceinline__ void ldsm4t(uint32_t addr, unsigned* r) {
    asm volatile("ldmatrix.sync.aligned.m8n8.x4.trans.shared.b16 {%0,%1,%2,%3}, [%4];"
        : "=r"(r[0]), "=r"(r[1]), "=r"(r[2]), "=r"(r[3]) : "r"(addr));
}

#define MMA_F16(c, a0, a1, a2, a3, b0, b1)                                    \
    asm volatile(                                                             \
        "mma.sync.aligned.m16n8k16.row.col.f32.f16.f16.f32 "                  \
        "{%0,%1,%2,%3},{%4,%5,%6,%7},{%8,%9},{%0,%1,%2,%3};"                  \
        : "+f"((c)[0]), "+f"((c)[1]), "+f"((c)[2]), "+f"((c)[3])              \
        : "r"(a0), "r"(a1), "r"(a2), "r"(a3), "r"(b0), "r"(b1))

// ---------------------------------------------------------------------------
// prep: one launch does x->fp16 and both weight transposes (fp32 -> fp16^T)
// ---------------------------------------------------------------------------
#define NB_F2H 6144
#define NB_T1  1728
#define NB_T2  576

__global__ void prep_kernel(const float* __restrict__ x,
                            const float* __restrict__ W1,
                            const float* __restrict__ W2,
                            __half* __restrict__ xh,
                            __half* __restrict__ wt1,
                            __half* __restrict__ wt2)
{
    const int bid = blockIdx.x;
    const int tid = threadIdx.x;
    if (bid < NB_F2H) {
        int i = (bid * 256 + tid) * 4;
        float4 v = *(const float4*)(x + i);
        uint2 u = { packf(v.x, v.y), packf(v.z, v.w) };
        *(uint2*)(xh + i) = u;
    } else {
        __shared__ __half t[32][33];
        const float* W; __half* Wt; int N, b;
        if (bid < NB_F2H + NB_T1) { W = W1; Wt = wt1; N = E3; b = bid - NB_F2H; }
        else                      { W = W2; Wt = wt2; N = EE; b = bid - NB_F2H - NB_T1; }
        const int K = EE;
        const int nbx = N / 32;
        const int n0 = (b % nbx) * 32, k0 = (b / nbx) * 32;
        const int tx = tid & 31, ty = tid >> 5;
#pragma unroll
        for (int i = 0; i < 32; i += 8)
            t[ty + i][tx] = __float2half(W[(size_t)(k0 + ty + i) * N + n0 + tx]);
        __syncthreads();
#pragma unroll
        for (int i = 0; i < 32; i += 8)
            Wt[(size_t)(n0 + ty + i) * K + k0 + tx] = t[tx][ty + i];
    }
}

// ---------------------------------------------------------------------------
// FP16 GEMM: C[M,N] = A[M,K] @ Wt[N,K]^T + bias
// Tile 128(M) x TN(N), BK=64, 3-stage cp.async pipeline, 256 threads (8 warps),
// 4 warps along M x 2 along N (warp tile 32 x TN/2). Fragment ring on B.
// TN=128 for QKV (big grid), TN=64 for proj (wave-quantization fix).
// ---------------------------------------------------------------------------
#define GP 72
#define GA(s) ((s) * 9216)

template<int HALF_OUT, int TN>
__global__ __launch_bounds__(256, 2) void gemm_f16(
    const __half* __restrict__ A, const __half* __restrict__ Bt,
    const float* __restrict__ bias, void* __restrict__ Cv,
    int M, int N, int K)
{
    constexpr int BSTG = TN * GP;            // B stage size (halves)
    constexpr int NTP  = TN / 32;            // B fragment-pair tiles per warp
    constexpr int NSTEP = 4 * NTP;

    extern __shared__ __half sh[];
    const uint32_t sbase = smem_u32(sh);
    const int tid  = threadIdx.x;
    const int lane = tid & 31;
    const int warp = tid >> 5;
    const int grp  = lane >> 2;
    const int tid4 = lane & 3;
    const int wm = warp & 3;
    const int wn = warp >> 2;
    const int rowBase = blockIdx.y * 128;
    const int colBase = blockIdx.x * TN;

    const int lr = lane & 7, lt = lane >> 3;
    const uint32_t aoff0 = ((wm * 32 +      (lt & 1) * 8 + lr) * GP + (lt >> 1) * 8) * 2;
    const uint32_t aoff1 = ((wm * 32 + 16 + (lt & 1) * 8 + lr) * GP + (lt >> 1) * 8) * 2;
    const uint32_t boff0 = ((wn * (TN / 2) + (lt >> 1) * 8 + lr) * GP + (lt & 1) * 8) * 2;

    float acc[2][TN / 16][4];
#pragma unroll
    for (int mt = 0; mt < 2; mt++)
#pragma unroll
        for (int nt = 0; nt < TN / 16; nt++)
#pragma unroll
            for (int c = 0; c < 4; c++) acc[mt][nt][c] = 0.f;

    const int nc = K / 64;

#define GFILL(c_, st_) do {                                                            \
    const int k0_ = (c_) * 64;                                                         \
    _Pragma("unroll")                                                                  \
    for (int i_ = 0; i_ < 4; i_++) {                                                   \
        int idx_ = tid + 256 * i_;                                                     \
        int m_ = idx_ >> 3, kc_ = (idx_ & 7) * 8;                                      \
        cp16(sbase + (GA(st_) + m_ * GP + kc_) * 2,                                    \
             A + (size_t)(rowBase + m_) * K + k0_ + kc_);                              \
    }                                                                                  \
    _Pragma("unroll")                                                                  \
    for (int i_ = 0; i_ < TN / 32; i_++) {                                             \
        int idx_ = tid + 256 * i_;                                                     \
        int n_ = idx_ >> 3, kc_ = (idx_ & 7) * 8;                                      \
        cp16(sbase + (27648 + (st_) * BSTG + n_ * GP + kc_) * 2,                       \
             Bt + (size_t)(colBase + n_) * K + k0_ + kc_);                             \
    }                                                                                  \
    CP_COMMIT();                                                                       \
} while (0)

    GFILL(0, 0);
    GFILL(1, 1);

    for (int c = 0; c < nc; c++) {
        if (c + 2 < nc) CP_WAIT1(); else CP_WAIT0();
        __syncthreads();
        if (c + 2 < nc) GFILL(c + 2, (c + 2) % 3);

        const int s = c % 3;
        const uint32_t baseA = sbase + GA(s) * 2;
        const uint32_t baseB = sbase + (27648 + s * BSTG) * 2;

        unsigned afr[2][2][4];
        ldsm4(baseA + aoff0, afr[0][0]);
        ldsm4(baseA + aoff1, afr[0][1]);
        unsigned bb[3][4];
        ldsm4(baseB + boff0 + (0 % NTP) * (16 * GP * 2) + (0 / NTP) * 32, bb[0]);
        ldsm4(baseB + boff0 + (1 % NTP) * (16 * GP * 2) + (1 / NTP) * 32, bb[1]);

#pragma unroll
        for (int t = 0; t < NSTEP; t++) {
            const int kb = t / NTP, ntp = t % NTP, cur = kb & 1;
            if (ntp == 0 && kb < 3) {
                ldsm4(baseA + aoff0 + (kb + 1) * 32, afr[cur ^ 1][0]);
                ldsm4(baseA + aoff1 + (kb + 1) * 32, afr[cur ^ 1][1]);
            }
            if (t + 2 < NSTEP) {
                const int t2 = t + 2;
                ldsm4(baseB + boff0 + (t2 % NTP) * (16 * GP * 2) + (t2 / NTP) * 32,
                      bb[t2 % 3]);
            }
            const unsigned* aa0 = afr[cur][0];
            const unsigned* aa1 = afr[cur][1];
            const unsigned* cc  = bb[t % 3];
            MMA_F16(acc[0][2 * ntp],     aa0[0], aa0[1], aa0[2], aa0[3], cc[0], cc[1]);
            MMA_F16(acc[0][2 * ntp + 1], aa0[0], aa0[1], aa0[2], aa0[3], cc[2], cc[3]);
            MMA_F16(acc[1][2 * ntp],     aa1[0], aa1[1], aa1[2], aa1[3], cc[0], cc[1]);
            MMA_F16(acc[1][2 * ntp + 1], aa1[0], aa1[1], aa1[2], aa1[3], cc[2], cc[3]);
        }
    }
#undef GFILL

    // epilogue: + bias
#pragma unroll
    for (int mt = 0; mt < 2; mt++) {
        int r0 = rowBase + wm * 32 + mt * 16 + grp;
        int r1 = r0 + 8;
#pragma unroll
        for (int nt = 0; nt < TN / 16; nt++) {
            int col = colBase + wn * (TN / 2) + nt * 8 + 2 * tid4;
            float bx = bias[col], by = bias[col + 1];
            if (HALF_OUT) {
                __half* C = (__half*)Cv;
                *(unsigned*)&C[(size_t)r0 * N + col] = packf(acc[mt][nt][0] + bx, acc[mt][nt][1] + by);
                *(unsigned*)&C[(size_t)r1 * N + col] = packf(acc[mt][nt][2] + bx, acc[mt][nt][3] + by);
            } else {
                float* C = (float*)Cv;
                float2 o0 = { acc[mt][nt][0] + bx, acc[mt][nt][1] + by };
                float2 o1 = { acc[mt][nt][2] + bx, acc[mt][nt][3] + by };
                *(float2*)&C[(size_t)r0 * N + col] = o0;
                *(float2*)&C[(size_t)r1 * N + col] = o1;
            }
        }
    }
}

#define GEMM_SMEM_128 110592           // (27648 + 3*9216) halves * 2
#define GEMM_SMEM_64  82944            // (27648 + 3*4608) halves * 2

// ---------------------------------------------------------------------------
// Flash attention: fp16 MMA, register P, log2-domain half2 softmax,
// hoisted Q fragments, deferred (per-lane) l-sum, direct ldsm loads.
// 3-stage cp.async K/V pipeline. 256 threads = 8 warps (16 q rows each).
// ---------------------------------------------------------------------------
#define AKo 9216
#define AVo 23040
#define ATTN_SMEM 73728

#define ATTN_FILL(j_, st_) do {                                                        \
    const int kr_ = (j_) * 64;                                                         \
    _Pragma("unroll")                                                                  \
    for (int i_ = 0; i_ < 2; i_++) {                                                   \
        int idx_ = tid + 256 * i_;                                                     \
        int r_ = idx_ >> 3, c16_ = (idx_ & 7) * 8;                                     \
        cp16(sbase + (AKo + (st_) * 4608 + r_ * GP + c16_) * 2,                        \
             &g_qkv[base + (size_t)(kr_ + r_) * E3 + EE + c16_]);                      \
        cp16(sbase + (AVo + (st_) * 4608 + r_ * GP + c16_) * 2,                        \
             &g_qkv[base + (size_t)(kr_ + r_) * E3 + 2 * EE + c16_]);                  \
    }                                                                                  \
    CP_COMMIT();                                                                       \
} while (0)

__global__ __launch_bounds__(256, 2) void attn_f16_kernel()
{
    extern __shared__ __half sh[];
    const uint32_t sbase = smem_u32(sh);

    const int tid  = threadIdx.x;
    const int lane = tid & 31;
    const int warp = tid >> 5;
    const int grp  = lane >> 2;
    const int tid4 = lane & 3;
    const int w16  = warp * 16;

    const int qt = (int)gridDim.x - 1 - (int)blockIdx.x;   // heaviest tiles first
    const int bh = blockIdx.y;
    const int b = bh / HH, h = bh % HH;
    const int q0 = qt * 128;

    const size_t base = (size_t)b * TT * E3 + (size_t)h * DD;

    const int lr = lane & 7, lt = lane >> 3;
    const uint32_t qoff  = ((w16 + (lt & 1) * 8 + lr) * GP + (lt >> 1) * 8) * 2;
    const uint32_t koff0 = (((lt >> 1) * 8 + lr) * GP + (lt & 1) * 8) * 2;
    const uint32_t voff0 = (((lt & 1) * 8 + lr) * GP + (lt >> 1) * 8) * 2;

    // load Q tile (128x64), scale 0.125*log2(e) folded in (log2-domain scores)
    const float SC = 0.125f * 1.4426950408889634f;
#pragma unroll
    for (int i = tid; i < 2048; i += 256) {
        int r = i >> 4, c4 = (i & 15) * 4;
        uint2 u = *(const uint2*)&g_qkv[base + (size_t)(q0 + r) * E3 + c4];
        float2 f0 = __half22float2(*(__half2*)&u.x);
        float2 f1 = __half22float2(*(__half2*)&u.y);
        uint2 o = { packf(f0.x * SC, f0.y * SC), packf(f1.x * SC, f1.y * SC) };
        *(uint2*)&sh[r * GP + c4] = o;
    }

    const int njt = 2 * qt + 2;
    ATTN_FILL(0, 0);
    if (njt > 1) ATTN_FILL(1, 1);

    __syncthreads();                 // Q stores visible before hoisted ldsm

    // hoist Q fragments: 16 regs, reused for every k tile
    unsigned qfr[4][4];
#pragma unroll
    for (int kb = 0; kb < 4; kb++) ldsm4(sbase + qoff + kb * 32, qfr[kb]);

    float oacc[8][4];
    float mrow[2] = { -1e30f, -1e30f };
    float lrow[2] = { 0.f, 0.f };    // per-lane partial sums; reduced at epilogue
#pragma unroll
    for (int nt = 0; nt < 8; nt++)
#pragma unroll
        for (int c = 0; c < 4; c++) oacc[nt][c] = 0.f;

    for (int jt = 0; jt < njt; jt++) {
        const int k0 = jt * 64;
        if (jt + 2 < njt) CP_WAIT1(); else CP_WAIT0();
        __syncthreads();
        if (jt + 2 < njt) ATTN_FILL(jt + 2, (jt + 2) % 3);

        const bool active = (k0 <= q0 + w16 + 15);
        if (active) {
            const int st = jt % 3;
            const uint32_t baseK = sbase + (AKo + st * 4608) * 2;
            const uint32_t baseV = sbase + (AVo + st * 4608) * 2;

            // ---- S = Q K^T (log2 domain) ----
            float sacc[8][4];
#pragma unroll
            for (int nt = 0; nt < 8; nt++)
#pragma unroll
                for (int c = 0; c < 4; c++) sacc[nt][c] = 0.f;

#pragma unroll
            for (int kk = 0; kk < 4; kk++) {
                const unsigned* q = qfr[kk];
#pragma unroll
                for (int ntp = 0; ntp < 4; ntp++) {
                    unsigned cc[4];
                    ldsm4(baseK + koff0 + ntp * (16 * GP * 2) + kk * 32, cc);
                    MMA_F16(sacc[2 * ntp],     q[0], q[1], q[2], q[3], cc[0], cc[1]);
                    MMA_F16(sacc[2 * ntp + 1], q[0], q[1], q[2], q[3], cc[2], cc[3]);
                }
            }

            // causal mask
            if (k0 + 63 > q0 + w16) {
#pragma unroll
                for (int nt = 0; nt < 8; nt++)
#pragma unroll
                    for (int c = 0; c < 4; c++) {
                        int row = q0 + w16 + grp + 8 * (c >> 1);
                        int col = k0 + nt * 8 + 2 * tid4 + (c & 1);
                        if (col > row) sacc[nt][c] = -1e30f;
                    }
            }

            // ---- online softmax (base 2); P = h2exp2 -> fp16 A-fragments ----
            unsigned pr[8][2];
#pragma unroll
            for (int p = 0; p < 2; p++) {
                float mx = -1e30f;
#pragma unroll
                for (int nt = 0; nt < 8; nt++)
                    mx = fmaxf(mx, fmaxf(sacc[nt][2 * p], sacc[nt][2 * p + 1]));
                mx = fmaxf(mx, __shfl_xor_sync(0xffffffffu, mx, 1));
                mx = fmaxf(mx, __shfl_xor_sync(0xffffffffu, mx, 2));
                float mnew = fmaxf(mrow[p], mx);
                float alpha = exp2f(mrow[p] - mnew);
                mrow[p] = mnew;
                float sum = 0.f;
#pragma unroll
                for (int nt = 0; nt < 8; nt++) {
                    __half2 d = __floats2half2_rn(sacc[nt][2 * p]     - mnew,
                                                  sacc[nt][2 * p + 1] - mnew);
                    __half2 e = h2exp2(d);
                    pr[nt][p] = h2bits(e);
                    float2 ef = __half22float2(e);
                    sum += ef.x + ef.y;
                }
                lrow[p] = lrow[p] * alpha + sum;   // per-lane partial (no shuffles)
#pragma unroll
                for (int nt = 0; nt < 8; nt++) {
                    oacc[nt][2 * p]     *= alpha;
                    oacc[nt][2 * p + 1] *= alpha;
                }
            }

            // ---- O += P V (V via ldmatrix.trans) ----
#pragma unroll
            for (int s4 = 0; s4 < 4; s4++) {
#pragma unroll
                for (int ntp = 0; ntp < 4; ntp++) {
                    unsigned cc[4];
                    ldsm4t(baseV + voff0 + s4 * (16 * GP * 2) + ntp * 32, cc);
                    MMA_F16(oacc[2 * ntp],     pr[2 * s4][0], pr[2 * s4][1],
                            pr[2 * s4 + 1][0], pr[2 * s4 + 1][1], cc[0], cc[1]);
                    MMA_F16(oacc[2 * ntp + 1], pr[2 * s4][0], pr[2 * s4][1],
                            pr[2 * s4 + 1][0], pr[2 * s4 + 1][1], cc[2], cc[3]);
                }
            }
        }
    }

    // epilogue: reduce lrow across the 4-lane group, normalize, write y (fp16)
#pragma unroll
    for (int p = 0; p < 2; p++) {
        lrow[p] += __shfl_xor_sync(0xffffffffu, lrow[p], 1);
        lrow[p] += __shfl_xor_sync(0xffffffffu, lrow[p], 2);
    }
    float inv0 = 1.0f / lrow[0];
    float inv1 = 1.0f / lrow[1];
    int r0 = q0 + w16 + grp;
    int r1 = r0 + 8;
#pragma unroll
    for (int nt = 0; nt < 8; nt++) {
        int col = h * DD + nt * 8 + 2 * tid4;
        *(unsigned*)&g_y[((size_t)b * TT + r0) * EE + col] =
            packf(oacc[nt][0] * inv0, oacc[nt][1] * inv0);
        *(unsigned*)&g_y[((size_t)b * TT + r1) * EE + col] =
            packf(oacc[nt][2] * inv1, oacc[nt][3] * inv1);
    }
}

// ---------------------------------------------------------------------------
extern "C" void kernel_launch(void* const* d_in, const int* in_sizes, int n_in,
                              void* d_out, int out_size)
{
    const float* x      = (const float*)d_in[0];
    const float* W_attn = (const float*)d_in[1];
    const float* b_attn = (const float*)d_in[2];
    const float* W_proj = (const float*)d_in[3];
    const float* b_proj = (const float*)d_in[4];
    float* out = (float*)d_out;

    __half *xh, *qkv, *y, *wt1, *wt2;
    cudaGetSymbolAddress((void**)&xh,  g_xh);
    cudaGetSymbolAddress((void**)&qkv, g_qkv);
    cudaGetSymbolAddress((void**)&y,   g_y);
    cudaGetSymbolAddress((void**)&wt1, g_wt1);
    cudaGetSymbolAddress((void**)&wt2, g_wt2);

    cudaFuncSetAttribute((const void*)gemm_f16<1, 128>,
                         cudaFuncAttributeMaxDynamicSharedMemorySize, GEMM_SMEM_128);
    cudaFuncSetAttribute((const void*)gemm_f16<0, 64>,
                         cudaFuncAttributeMaxDynamicSharedMemorySize, GEMM_SMEM_64);
    cudaFuncSetAttribute(attn_f16_kernel,
                         cudaFuncAttributeMaxDynamicSharedMemorySize, ATTN_SMEM);

    // 0) prep: x -> fp16, weights -> fp16 K-major transpose
    prep_kernel<<<NB_F2H + NB_T1 + NB_T2, 256>>>(x, W_attn, W_proj, xh, wt1, wt2);

    // 1) QKV projection: [8192,768] @ [768,2304] + b  -> qkv (fp16)
    gemm_f16<1, 128><<<dim3(E3 / 128, MTOT / 128), 256, GEMM_SMEM_128>>>(
        xh, wt1, b_attn, qkv, MTOT, E3, EE);

    // 2) causal flash attention -> y (fp16)
    attn_f16_kernel<<<dim3(TT / 128, BB * HH), 256, ATTN_SMEM>>>();

    // 3) output projection (128x64 tiles vs wave quantization): -> out (fp32)
    gemm_f16<0, 64><<<dim3(EE / 64, MTOT / 128), 256, GEMM_SMEM_64>>>(
        y, wt2, b_proj, out, MTOT, EE, EE);
}

// round 15
// speedup vs baseline: 9.0863x; 1.0461x over previous
#include <cuda_runtime.h>
#include <cuda_fp16.h>
#include <cstdint>

#define BB 2
#define TT 4096
#define EE 768
#define HH 12
#define DD 64
#define E3 (3*EE)
#define MTOT (BB*TT)

// Scratch (allocation-free rule: __device__ globals)
__device__ __half g_xh [(size_t)MTOT*EE];   // x in fp16
__device__ __half g_qkv[(size_t)MTOT*E3];   // [B,T,3E] fp16
__device__ __half g_y  [(size_t)MTOT*EE];   // attention out fp16
__device__ __half g_wt1[(size_t)E3*EE];     // W_attn^T [2304][768] fp16 (K-major)
__device__ __half g_wt2[(size_t)EE*EE];     // W_proj^T [768][768]  fp16 (K-major)

// ---------------------------------------------------------------------------
// helpers
// ---------------------------------------------------------------------------
__device__ __forceinline__ uint32_t smem_u32(const void* p) {
    uint32_t a;
    asm("{ .reg .u64 t; cvta.to.shared.u64 t, %1; cvt.u32.u64 %0, t; }" : "=r"(a) : "l"(p));
    return a;
}
__device__ __forceinline__ void cp16(uint32_t saddr, const void* g) {
    asm volatile("cp.async.cg.shared.global [%0], [%1], 16;" :: "r"(saddr), "l"(g));
}
#define CP_COMMIT() asm volatile("cp.async.commit_group;" ::: "memory")
#define CP_WAIT0()  asm volatile("cp.async.wait_group 0;" ::: "memory")
#define CP_WAIT1()  asm volatile("cp.async.wait_group 1;" ::: "memory")

__device__ __forceinline__ unsigned h2bits(__half2 h) { return *(unsigned*)&h; }
__device__ __forceinline__ unsigned packf(float a, float b) {
    __half2 h = __floats2half2_rn(a, b);
    return *(unsigned*)&h;
}

__device__ __forceinline__ void ldsm4(uint32_t addr, unsigned* r) {
    asm volatile("ldmatrix.sync.aligned.m8n8.x4.shared.b16 {%0,%1,%2,%3}, [%4];"
        : "=r"(r[0]), "=r"(r[1]), "=r"(r[2]), "=r"(r[3]) : "r"(addr));
}
__device__ __forceinline__ void ldsm4t(uint32_t addr, unsigned* r) {
    asm volatile("ldmatrix.sync.aligned.m8n8.x4.trans.shared.b16 {%0,%1,%2,%3}, [%4];"
        : "=r"(r[0]), "=r"(r[1]), "=r"(r[2]), "=r"(r[3]) : "r"(addr));
}

#define MMA_F16(c, a0, a1, a2, a3, b0, b1)                                    \
    asm volatile(                                                             \
        "mma.sync.aligned.m16n8k16.row.col.f32.f16.f16.f32 "                  \
        "{%0,%1,%2,%3},{%4,%5,%6,%7},{%8,%9},{%0,%1,%2,%3};"                  \
        : "+f"((c)[0]), "+f"((c)[1]), "+f"((c)[2]), "+f"((c)[3])              \
        : "r"(a0), "r"(a1), "r"(a2), "r"(a3), "r"(b0), "r"(b1))

// ---------------------------------------------------------------------------
// prep: one launch does x->fp16 and both weight transposes (fp32 -> fp16^T)
// ---------------------------------------------------------------------------
#define NB_F2H 6144
#define NB_T1  1728
#define NB_T2  576

__global__ void prep_kernel(const float* __restrict__ x,
                            const float* __restrict__ W1,
                            const float* __restrict__ W2,
                            __half* __restrict__ xh,
                            __half* __restrict__ wt1,
                            __half* __restrict__ wt2)
{
    const int bid = blockIdx.x;
    const int tid = threadIdx.x;
    if (bid < NB_F2H) {
        int i = (bid * 256 + tid) * 4;
        float4 v = *(const float4*)(x + i);
        uint2 u = { packf(v.x, v.y), packf(v.z, v.w) };
        *(uint2*)(xh + i) = u;
    } else {
        __shared__ __half t[32][33];
        const float* W; __half* Wt; int N, b;
        if (bid < NB_F2H + NB_T1) { W = W1; Wt = wt1; N = E3; b = bid - NB_F2H; }
        else                      { W = W2; Wt = wt2; N = EE; b = bid - NB_F2H - NB_T1; }
        const int K = EE;
        const int nbx = N / 32;
        const int n0 = (b % nbx) * 32, k0 = (b / nbx) * 32;
        const int tx = tid & 31, ty = tid >> 5;
#pragma unroll
        for (int i = 0; i < 32; i += 8)
            t[ty + i][tx] = __float2half(W[(size_t)(k0 + ty + i) * N + n0 + tx]);
        __syncthreads();
#pragma unroll
        for (int i = 0; i < 32; i += 8)
            Wt[(size_t)(n0 + ty + i) * K + k0 + tx] = t[tx][ty + i];
    }
}

// ---------------------------------------------------------------------------
// FP16 GEMM: C[M,N] = A[M,K] @ Wt[N,K]^T + bias
// Tile 128x128, BK=64, 3-stage cp.async pipeline, 256 threads (8 warps),
// warp tile 32x64, ldmatrix fragments with B ring.
// ---------------------------------------------------------------------------
#define GP 72
#define GA(s) ((s) * 9216)
#define GEMM_SMEM 110592               // (27648 + 3*9216) halves * 2

template<int HALF_OUT>
__global__ __launch_bounds__(256, 2) void gemm_f16(
    const __half* __restrict__ A, const __half* __restrict__ Bt,
    const float* __restrict__ bias, void* __restrict__ Cv,
    int M, int N, int K)
{
    extern __shared__ __half sh[];
    const uint32_t sbase = smem_u32(sh);
    const int tid  = threadIdx.x;
    const int lane = tid & 31;
    const int warp = tid >> 5;
    const int grp  = lane >> 2;
    const int tid4 = lane & 3;
    const int wm = warp & 3;
    const int wn = warp >> 2;
    const int rowBase = blockIdx.y * 128;
    const int colBase = blockIdx.x * 128;

    const int lr = lane & 7, lt = lane >> 3;
    const uint32_t aoff0 = ((wm * 32 +      (lt & 1) * 8 + lr) * GP + (lt >> 1) * 8) * 2;
    const uint32_t aoff1 = ((wm * 32 + 16 + (lt & 1) * 8 + lr) * GP + (lt >> 1) * 8) * 2;
    const uint32_t boff0 = ((wn * 64 + (lt >> 1) * 8 + lr) * GP + (lt & 1) * 8) * 2;

    float acc[2][8][4];
#pragma unroll
    for (int mt = 0; mt < 2; mt++)
#pragma unroll
        for (int nt = 0; nt < 8; nt++)
#pragma unroll
            for (int c = 0; c < 4; c++) acc[mt][nt][c] = 0.f;

    const int nc = K / 64;

#define GFILL(c_, st_) do {                                                            \
    const int k0_ = (c_) * 64;                                                         \
    _Pragma("unroll")                                                                  \
    for (int i_ = 0; i_ < 4; i_++) {                                                   \
        int idx_ = tid + 256 * i_;                                                     \
        int m_ = idx_ >> 3, kc_ = (idx_ & 7) * 8;                                      \
        cp16(sbase + (GA(st_) + m_ * GP + kc_) * 2,                                    \
             A + (size_t)(rowBase + m_) * K + k0_ + kc_);                              \
        cp16(sbase + (27648 + (st_) * 9216 + m_ * GP + kc_) * 2,                       \
             Bt + (size_t)(colBase + m_) * K + k0_ + kc_);                             \
    }                                                                                  \
    CP_COMMIT();                                                                       \
} while (0)

    GFILL(0, 0);
    GFILL(1, 1);

    for (int c = 0; c < nc; c++) {
        if (c + 2 < nc) CP_WAIT1(); else CP_WAIT0();
        __syncthreads();
        if (c + 2 < nc) GFILL(c + 2, (c + 2) % 3);

        const int s = c % 3;
        const uint32_t baseA = sbase + GA(s) * 2;
        const uint32_t baseB = sbase + (27648 + s * 9216) * 2;

        unsigned afr[2][2][4];
        ldsm4(baseA + aoff0, afr[0][0]);
        ldsm4(baseA + aoff1, afr[0][1]);
        unsigned bb[3][4];
        ldsm4(baseB + boff0,                 bb[0]);
        ldsm4(baseB + boff0 + (16 * GP * 2), bb[1]);

#pragma unroll
        for (int t = 0; t < 16; t++) {
            const int kb = t >> 2, ntp = t & 3, cur = kb & 1;
            if (ntp == 0 && kb < 3) {
                ldsm4(baseA + aoff0 + (kb + 1) * 32, afr[cur ^ 1][0]);
                ldsm4(baseA + aoff1 + (kb + 1) * 32, afr[cur ^ 1][1]);
            }
            if (t + 2 < 16) {
                const int t2 = t + 2;
                ldsm4(baseB + boff0 + (t2 & 3) * (16 * GP * 2) + (t2 >> 2) * 32,
                      bb[t2 % 3]);
            }
            const unsigned* aa0 = afr[cur][0];
            const unsigned* aa1 = afr[cur][1];
            const unsigned* cc  = bb[t % 3];
            MMA_F16(acc[0][2 * ntp],     aa0[0], aa0[1], aa0[2], aa0[3], cc[0], cc[1]);
            MMA_F16(acc[0][2 * ntp + 1], aa0[0], aa0[1], aa0[2], aa0[3], cc[2], cc[3]);
            MMA_F16(acc[1][2 * ntp],     aa1[0], aa1[1], aa1[2], aa1[3], cc[0], cc[1]);
            MMA_F16(acc[1][2 * ntp + 1], aa1[0], aa1[1], aa1[2], aa1[3], cc[2], cc[3]);
        }
    }
#undef GFILL

    // epilogue: + bias
#pragma unroll
    for (int mt = 0; mt < 2; mt++) {
        int r0 = rowBase + wm * 32 + mt * 16 + grp;
        int r1 = r0 + 8;
#pragma unroll
        for (int nt = 0; nt < 8; nt++) {
            int col = colBase + wn * 64 + nt * 8 + 2 * tid4;
            float bx = bias[col], by = bias[col + 1];
            if (HALF_OUT) {
                __half* C = (__half*)Cv;
                *(unsigned*)&C[(size_t)r0 * N + col] = packf(acc[mt][nt][0] + bx, acc[mt][nt][1] + by);
                *(unsigned*)&C[(size_t)r1 * N + col] = packf(acc[mt][nt][2] + bx, acc[mt][nt][3] + by);
            } else {
                float* C = (float*)Cv;
                float2 o0 = { acc[mt][nt][0] + bx, acc[mt][nt][1] + by };
                float2 o1 = { acc[mt][nt][2] + bx, acc[mt][nt][3] + by };
                *(float2*)&C[(size_t)r0 * N + col] = o0;
                *(float2*)&C[(size_t)r1 * N + col] = o1;
            }
        }
    }
}

// ---------------------------------------------------------------------------
// Flash attention: fp16 MMA, register P, log2-domain half2 softmax,
// hoisted Q fragments, TENSOR-CORE row sums (P @ ones via MMA).
// 3-stage cp.async K/V pipeline. 256 threads = 8 warps (16 q rows each).
// ---------------------------------------------------------------------------
#define AKo 9216
#define AVo 23040
#define ATTN_SMEM 73728

#define ATTN_FILL(j_, st_) do {                                                        \
    const int kr_ = (j_) * 64;                                                         \
    _Pragma("unroll")                                                                  \
    for (int i_ = 0; i_ < 2; i_++) {                                                   \
        int idx_ = tid + 256 * i_;                                                     \
        int r_ = idx_ >> 3, c16_ = (idx_ & 7) * 8;                                     \
        cp16(sbase + (AKo + (st_) * 4608 + r_ * GP + c16_) * 2,                        \
             &g_qkv[base + (size_t)(kr_ + r_) * E3 + EE + c16_]);                      \
        cp16(sbase + (AVo + (st_) * 4608 + r_ * GP + c16_) * 2,                        \
             &g_qkv[base + (size_t)(kr_ + r_) * E3 + 2 * EE + c16_]);                  \
    }                                                                                  \
    CP_COMMIT();                                                                       \
} while (0)

__global__ __launch_bounds__(256, 2) void attn_f16_kernel()
{
    extern __shared__ __half sh[];
    const uint32_t sbase = smem_u32(sh);

    const int tid  = threadIdx.x;
    const int lane = tid & 31;
    const int warp = tid >> 5;
    const int grp  = lane >> 2;
    const int tid4 = lane & 3;
    const int w16  = warp * 16;

    const int qt = (int)gridDim.x - 1 - (int)blockIdx.x;   // heaviest tiles first
    const int bh = blockIdx.y;
    const int b = bh / HH, h = bh % HH;
    const int q0 = qt * 128;

    const size_t base = (size_t)b * TT * E3 + (size_t)h * DD;

    const int lr = lane & 7, lt = lane >> 3;
    const uint32_t qoff  = ((w16 + (lt & 1) * 8 + lr) * GP + (lt >> 1) * 8) * 2;
    const uint32_t koff0 = (((lt >> 1) * 8 + lr) * GP + (lt & 1) * 8) * 2;
    const uint32_t voff0 = (((lt & 1) * 8 + lr) * GP + (lt >> 1) * 8) * 2;

    // load Q tile (128x64), scale 0.125*log2(e) folded in (log2-domain scores)
    const float SC = 0.125f * 1.4426950408889634f;
#pragma unroll
    for (int i = tid; i < 2048; i += 256) {
        int r = i >> 4, c4 = (i & 15) * 4;
        uint2 u = *(const uint2*)&g_qkv[base + (size_t)(q0 + r) * E3 + c4];
        float2 f0 = __half22float2(*(__half2*)&u.x);
        float2 f1 = __half22float2(*(__half2*)&u.y);
        uint2 o = { packf(f0.x * SC, f0.y * SC), packf(f1.x * SC, f1.y * SC) };
        *(uint2*)&sh[r * GP + c4] = o;
    }

    const int njt = 2 * qt + 2;
    ATTN_FILL(0, 0);
    if (njt > 1) ATTN_FILL(1, 1);

    __syncthreads();                 // Q stores visible before hoisted ldsm

    // hoist Q fragments: 16 regs, reused for every k tile
    unsigned qfr[4][4];
#pragma unroll
    for (int kb = 0; kb < 4; kb++) ldsm4(sbase + qoff + kb * 32, qfr[kb]);

    float oacc[8][4];
    float mrow[2] = { -1e30f, -1e30f };
    float lrow[2] = { 0.f, 0.f };    // exact per-lane row sums (from sum-MMA)
#pragma unroll
    for (int nt = 0; nt < 8; nt++)
#pragma unroll
        for (int c = 0; c < 4; c++) oacc[nt][c] = 0.f;

    const unsigned ONE2 = 0x3C003C00u;   // half2(1.0, 1.0)

    for (int jt = 0; jt < njt; jt++) {
        const int k0 = jt * 64;
        if (jt + 2 < njt) CP_WAIT1(); else CP_WAIT0();
        __syncthreads();
        if (jt + 2 < njt) ATTN_FILL(jt + 2, (jt + 2) % 3);

        const bool active = (k0 <= q0 + w16 + 15);
        if (active) {
            const int st = jt % 3;
            const uint32_t baseK = sbase + (AKo + st * 4608) * 2;
            const uint32_t baseV = sbase + (AVo + st * 4608) * 2;

            // ---- S = Q K^T (log2 domain) ----
            float sacc[8][4];
#pragma unroll
            for (int nt = 0; nt < 8; nt++)
#pragma unroll
                for (int c = 0; c < 4; c++) sacc[nt][c] = 0.f;

#pragma unroll
            for (int kk = 0; kk < 4; kk++) {
                const unsigned* q = qfr[kk];
#pragma unroll
                for (int ntp = 0; ntp < 4; ntp++) {
                    unsigned cc[4];
                    ldsm4(baseK + koff0 + ntp * (16 * GP * 2) + kk * 32, cc);
                    MMA_F16(sacc[2 * ntp],     q[0], q[1], q[2], q[3], cc[0], cc[1]);
                    MMA_F16(sacc[2 * ntp + 1], q[0], q[1], q[2], q[3], cc[2], cc[3]);
                }
            }

            // causal mask
            if (k0 + 63 > q0 + w16) {
#pragma unroll
                for (int nt = 0; nt < 8; nt++)
#pragma unroll
                    for (int c = 0; c < 4; c++) {
                        int row = q0 + w16 + grp + 8 * (c >> 1);
                        int col = k0 + nt * 8 + 2 * tid4 + (c & 1);
                        if (col > row) sacc[nt][c] = -1e30f;
                    }
            }

            // ---- online softmax (base 2); P = h2exp2 -> fp16 A-fragments ----
            unsigned pr[8][2];
            float alpha[2];
#pragma unroll
            for (int p = 0; p < 2; p++) {
                float mx = -1e30f;
#pragma unroll
                for (int nt = 0; nt < 8; nt++)
                    mx = fmaxf(mx, fmaxf(sacc[nt][2 * p], sacc[nt][2 * p + 1]));
                mx = fmaxf(mx, __shfl_xor_sync(0xffffffffu, mx, 1));
                mx = fmaxf(mx, __shfl_xor_sync(0xffffffffu, mx, 2));
                float mnew = fmaxf(mrow[p], mx);
                alpha[p] = exp2f(mrow[p] - mnew);
                mrow[p] = mnew;
#pragma unroll
                for (int nt = 0; nt < 8; nt++) {
                    __half2 d = __floats2half2_rn(sacc[nt][2 * p]     - mnew,
                                                  sacc[nt][2 * p + 1] - mnew);
                    pr[nt][p] = h2bits(h2exp2(d));
                }
#pragma unroll
                for (int nt = 0; nt < 8; nt++) {
                    oacc[nt][2 * p]     *= alpha[p];
                    oacc[nt][2 * p + 1] *= alpha[p];
                }
            }

            // ---- row sums via tensor core: lsum = P @ ones ----
            float ssum[4] = { 0.f, 0.f, 0.f, 0.f };
#pragma unroll
            for (int s4 = 0; s4 < 4; s4++)
                MMA_F16(ssum, pr[2 * s4][0], pr[2 * s4][1],
                        pr[2 * s4 + 1][0], pr[2 * s4 + 1][1], ONE2, ONE2);
            lrow[0] = lrow[0] * alpha[0] + ssum[0];
            lrow[1] = lrow[1] * alpha[1] + ssum[2];

            // ---- O += P V (V via ldmatrix.trans) ----
#pragma unroll
            for (int s4 = 0; s4 < 4; s4++) {
#pragma unroll
                for (int ntp = 0; ntp < 4; ntp++) {
                    unsigned cc[4];
                    ldsm4t(baseV + voff0 + s4 * (16 * GP * 2) + ntp * 32, cc);
                    MMA_F16(oacc[2 * ntp],     pr[2 * s4][0], pr[2 * s4][1],
                            pr[2 * s4 + 1][0], pr[2 * s4 + 1][1], cc[0], cc[1]);
                    MMA_F16(oacc[2 * ntp + 1], pr[2 * s4][0], pr[2 * s4][1],
                            pr[2 * s4 + 1][0], pr[2 * s4 + 1][1], cc[2], cc[3]);
                }
            }
        }
    }

    // epilogue: lrow is already the exact full row sum in every lane
    float inv0 = 1.0f / lrow[0];
    float inv1 = 1.0f / lrow[1];
    int r0 = q0 + w16 + grp;
    int r1 = r0 + 8;
#pragma unroll
    for (int nt = 0; nt < 8; nt++) {
        int col = h * DD + nt * 8 + 2 * tid4;
        *(unsigned*)&g_y[((size_t)b * TT + r0) * EE + col] =
            packf(oacc[nt][0] * inv0, oacc[nt][1] * inv0);
        *(unsigned*)&g_y[((size_t)b * TT + r1) * EE + col] =
            packf(oacc[nt][2] * inv1, oacc[nt][3] * inv1);
    }
}

// ---------------------------------------------------------------------------
extern "C" void kernel_launch(void* const* d_in, const int* in_sizes, int n_in,
                              void* d_out, int out_size)
{
    const float* x      = (const float*)d_in[0];
    const float* W_attn = (const float*)d_in[1];
    const float* b_attn = (const float*)d_in[2];
    const float* W_proj = (const float*)d_in[3];
    const float* b_proj = (const float*)d_in[4];
    float* out = (float*)d_out;

    __half *xh, *qkv, *y, *wt1, *wt2;
    cudaGetSymbolAddress((void**)&xh,  g_xh);
    cudaGetSymbolAddress((void**)&qkv, g_qkv);
    cudaGetSymbolAddress((void**)&y,   g_y);
    cudaGetSymbolAddress((void**)&wt1, g_wt1);
    cudaGetSymbolAddress((void**)&wt2, g_wt2);

    cudaFuncSetAttribute((const void*)gemm_f16<1>,
                         cudaFuncAttributeMaxDynamicSharedMemorySize, GEMM_SMEM);
    cudaFuncSetAttribute((const void*)gemm_f16<0>,
                         cudaFuncAttributeMaxDynamicSharedMemorySize, GEMM_SMEM);
    cudaFuncSetAttribute(attn_f16_kernel,
                         cudaFuncAttributeMaxDynamicSharedMemorySize, ATTN_SMEM);

    // 0) prep: x -> fp16, weights -> fp16 K-major transpose
    prep_kernel<<<NB_F2H + NB_T1 + NB_T2, 256>>>(x, W_attn, W_proj, xh, wt1, wt2);

    // 1) QKV projection: [8192,768] @ [768,2304] + b  -> qkv (fp16)
    gemm_f16<1><<<dim3(E3 / 128, MTOT / 128), 256, GEMM_SMEM>>>(
        xh, wt1, b_attn, qkv, MTOT, E3, EE);

    // 2) causal flash attention -> y (fp16)
    attn_f16_kernel<<<dim3(TT / 128, BB * HH), 256, ATTN_SMEM>>>();

    // 3) output projection (128x128 tiles): -> out (fp32)
    gemm_f16<0><<<dim3(EE / 128, MTOT / 128), 256, GEMM_SMEM>>>(
        y, wt2, b_proj, out, MTOT, EE, EE);
}